// round 14
// baseline (speedup 1.0000x reference)
#include <cuda_runtime.h>
#include <cuda_bf16.h>
#include <cstdint>

#define DI __device__ __forceinline__

// tcgen05 exists only in the arch-specific (sm_103a/sm_100a) pass.
#if defined(__CUDA_ARCH_FEAT_SM103_ALL) || defined(__CUDA_ARCH_FEAT_SM100_ALL)
#define HAS_TCGEN05 1
#else
#define HAS_TCGEN05 0
#endif

// Problem sizes
constexpr int D  = 2048;
constexpr int Hh = 8192;
constexpr int R  = 16;
constexpr int M  = 8192;

// GEMM tiling (tcgen05 bf16 path): 256x128 tile, 2 CTAs/SM for overlap
constexpr int TM = 256, TN = 128, KC = 64, NSTAGE = 2;
constexpr int STAGE_BYTES = (TM + TN) * 128;            // 48 KB
constexpr int SMEM_GEMM   = NSTAGE * STAGE_BYTES + 1024;  // ~97 KB
constexpr uint32_t IDESC  = (1u << 4) | (1u << 7) | (1u << 10)  // F32, BF16, BF16
                          | ((TN / 8) << 17) | (8u << 24);      // N=128, M=128
constexpr uint64_t DESC_BASE_SW128 =
    (2ull << 61) | (1ull << 46) | (64ull << 32) | (1ull << 16);

// ---------------- scratch -----------------------------------------------
__device__ __nv_bfloat16 g_Kx[M * D];
__device__ __nv_bfloat16 g_Kwfc[Hh * D];
__device__ __nv_bfloat16 g_Kwpr[D * Hh];
__device__ float         g_h[(size_t)M * Hh];
__device__ __nv_bfloat16 g_Kh[(size_t)M * Hh];
// LoRA fold-in ext chunks, hi/lo split layout (cols 48..63 stay zero forever):
//   t side: [t_hi | t_hi | t_lo | 0],  L side: [L_hi | L_lo | L_hi | 0]
__device__ __nv_bfloat16 g_t1ext[M * 64];
__device__ __nv_bfloat16 g_t2ext[M * 64];
__device__ __nv_bfloat16 g_Lext1[Hh * 64];
__device__ __nv_bfloat16 g_Lext2[D * 64];
__device__ float         g_tpart[64 * M * R];  // 64 n-chunks for TN=128
__device__ unsigned      g_amax[4];            // static-zero; amax idempotent across replays
__device__ unsigned      g_cnt[M / 32];        // tpart completion counters (self-resetting)

// ---------------- common helpers ----------------------------------------
DI uint32_t smaddr(const void* p) { return (uint32_t)__cvta_generic_to_shared(p); }
DI void cp16(void* s, const void* g) {
    asm volatile("cp.async.cg.shared.global [%0], [%1], 16;\n" ::"r"(smaddr(s)), "l"(g));
}
DI void cp_commit() { asm volatile("cp.async.commit_group;\n"); }
template <int N> DI void cp_wait() { asm volatile("cp.async.wait_group %0;\n" ::"n"(N)); }

DI float warp_max(float v) {
    for (int o = 16; o; o >>= 1) v = fmaxf(v, __shfl_xor_sync(0xffffffffu, v, o));
    return v;
}
DI float load_scale(const unsigned* slot) {
    return fmaxf(__fdiv_rn(__uint_as_float(*slot), 127.0f), 1e-8f);
}
DI float qclamp(float v, float s) {
    return fminf(fmaxf(rintf(__fdiv_rn(v, s)), -127.f), 127.f);
}

// mma.sync fallback helpers (used only in non-'a' pass)
DI void ldm_x4(uint32_t& r0, uint32_t& r1, uint32_t& r2, uint32_t& r3, const void* s) {
    asm volatile("ldmatrix.sync.aligned.m8n8.x4.shared.b16 {%0,%1,%2,%3},[%4];"
                 : "=r"(r0), "=r"(r1), "=r"(r2), "=r"(r3) : "r"(smaddr(s)));
}
DI void mma16816(float* c, const uint32_t* a, const uint32_t* b) {
    asm volatile(
        "mma.sync.aligned.m16n8k16.row.col.f32.bf16.bf16.f32 "
        "{%0,%1,%2,%3},{%4,%5,%6,%7},{%8,%9},{%0,%1,%2,%3};"
        : "+f"(c[0]), "+f"(c[1]), "+f"(c[2]), "+f"(c[3])
        : "r"(a[0]), "r"(a[1]), "r"(a[2]), "r"(a[3]), "r"(b[0]), "r"(b[1]));
}

#if HAS_TCGEN05
DI uint64_t mkdesc(uint32_t a) { return DESC_BASE_SW128 | (uint64_t)((a >> 4) & 0x3FFF); }
DI void tc_mma(uint32_t d, uint64_t ad, uint64_t bd, uint32_t idesc, uint32_t en) {
    asm volatile(
        "{\n\t.reg .pred p;\n\tsetp.ne.u32 p, %4, 0;\n\t"
        "tcgen05.mma.cta_group::1.kind::f16 [%0], %1, %2, %3, {%5,%5,%5,%5}, p;\n\t}"
        :: "r"(d), "l"(ad), "l"(bd), "r"(idesc), "r"(en), "r"(0u) : "memory");
}
DI void tc_commit(uint32_t mbar) {
    asm volatile(
        "tcgen05.commit.cta_group::1.mbarrier::arrive::one.shared::cluster.b64 [%0];"
        :: "r"(mbar) : "memory");
}
DI void mbar_init(uint32_t a, uint32_t cnt) {
    asm volatile("mbarrier.init.shared.b64 [%0], %1;" ::"r"(a), "r"(cnt) : "memory");
}
DI void mbar_wait(uint32_t a, uint32_t parity) {
    asm volatile(
        "{\n\t.reg .pred P1;\n\t"
        "WAIT_%=:\n\t"
        "mbarrier.try_wait.parity.acquire.cta.shared::cta.b64 P1, [%0], %1, 0x989680;\n\t"
        "@P1 bra.uni DONE_%=;\n\t"
        "bra.uni WAIT_%=;\n\t"
        "DONE_%=:\n\t}"
        :: "r"(a), "r"(parity) : "memory");
}
DI void fence_async() { asm volatile("fence.proxy.async.shared::cta;" ::: "memory"); }
DI void tmem_fence_after() { asm volatile("tcgen05.fence::after_thread_sync;" ::: "memory"); }
DI void tmem_fence_before() { asm volatile("tcgen05.fence::before_thread_sync;" ::: "memory"); }
DI void tmem_wait_ld() { asm volatile("tcgen05.wait::ld.sync.aligned;" ::: "memory"); }

DI unsigned long long pk2(float a, float b) {
    unsigned long long r; asm("mov.b64 %0, {%1,%2};" : "=l"(r) : "f"(a), "f"(b)); return r;
}
DI void upk2(float& a, float& b, unsigned long long v) {
    asm("mov.b64 {%0,%1}, %2;" : "=f"(a), "=f"(b) : "l"(v));
}
DI unsigned long long fma2(unsigned long long a, unsigned long long b, unsigned long long c) {
    unsigned long long d;
    asm("fma.rn.f32x2 %0, %1, %2, %3;" : "=l"(d) : "l"(a), "l"(b), "l"(c));
    return d;
}

#define LDTM32(r, addr)                                                          \
    asm volatile(                                                                \
        "tcgen05.ld.sync.aligned.32x32b.x32.b32 "                                \
        "{%0,%1,%2,%3,%4,%5,%6,%7,%8,%9,%10,%11,%12,%13,%14,%15,"               \
        "%16,%17,%18,%19,%20,%21,%22,%23,%24,%25,%26,%27,%28,%29,%30,%31},[%32];"\
        : "=r"((r)[0]), "=r"((r)[1]), "=r"((r)[2]), "=r"((r)[3]),                \
          "=r"((r)[4]), "=r"((r)[5]), "=r"((r)[6]), "=r"((r)[7]),                \
          "=r"((r)[8]), "=r"((r)[9]), "=r"((r)[10]), "=r"((r)[11]),              \
          "=r"((r)[12]), "=r"((r)[13]), "=r"((r)[14]), "=r"((r)[15]),            \
          "=r"((r)[16]), "=r"((r)[17]), "=r"((r)[18]), "=r"((r)[19]),            \
          "=r"((r)[20]), "=r"((r)[21]), "=r"((r)[22]), "=r"((r)[23]),            \
          "=r"((r)[24]), "=r"((r)[25]), "=r"((r)[26]), "=r"((r)[27]),            \
          "=r"((r)[28]), "=r"((r)[29]), "=r"((r)[30]), "=r"((r)[31])             \
        : "r"(addr))
#endif  // HAS_TCGEN05

// ---------------- 1: merged amax (x -> slot0, w_fc -> slot1) --------------
__global__ void k_amax2(const float* __restrict__ p0, const float* __restrict__ p1) {
    const float* p = blockIdx.y ? p1 : p0;
    const long long n = (long long)M * D;
    float m = 0.0f;
    long long i = ((long long)blockIdx.x * blockDim.x + threadIdx.x) * 4;
    long long stride = (long long)gridDim.x * blockDim.x * 4;
    for (; i < n; i += stride) {
        float4 v = *(const float4*)(p + i);
        m = fmaxf(m, fmaxf(fmaxf(fabsf(v.x), fabsf(v.y)), fmaxf(fabsf(v.z), fabsf(v.w))));
    }
    m = warp_max(m);
    if ((threadIdx.x & 31) == 0) atomicMax(&g_amax[blockIdx.y], __float_as_uint(m));
}

// ---------------- 1b: single amax (w_proj -> slot2) -----------------------
__global__ void k_amax(const float* __restrict__ p, long long n, unsigned* __restrict__ slot) {
    float m = 0.0f;
    long long i = ((long long)blockIdx.x * blockDim.x + threadIdx.x) * 4;
    long long stride = (long long)gridDim.x * blockDim.x * 4;
    for (; i < n; i += stride) {
        float4 v = *(const float4*)(p + i);
        m = fmaxf(m, fmaxf(fmaxf(fabsf(v.x), fabsf(v.y)), fmaxf(fabsf(v.z), fabsf(v.w))));
    }
    m = warp_max(m);
    if ((threadIdx.x & 31) == 0) atomicMax(slot, __float_as_uint(m));
}

// ---------------- 2: quantize to integer-valued bf16 ----------------------
__global__ void k_quant(const float* __restrict__ p, __nv_bfloat16* __restrict__ q,
                        long long n, const unsigned* __restrict__ slot,
                        long long nblk) {
    float s = load_scale(slot);
    long long i = (long long)blockIdx.x * blockDim.x + threadIdx.x;
    long long stride = nblk * blockDim.x;
    long long n4 = n >> 2;
    for (; i < n4; i += stride) {
        float4 v = *(const float4*)(p + i * 4);
        float k0 = qclamp(v.x, s), k1 = qclamp(v.y, s);
        float k2 = qclamp(v.z, s), k3 = qclamp(v.w, s);
        ((__nv_bfloat162*)q)[i * 2]     = __halves2bfloat162(__float2bfloat16(k0), __float2bfloat16(k1));
        ((__nv_bfloat162*)q)[i * 2 + 1] = __halves2bfloat162(__float2bfloat16(k2), __float2bfloat16(k3));
    }
}

// ---------------- 2b: quant w_fc + build Lext1/Lext2 (hi/lo split) --------
__global__ void k_quantw1(const float* __restrict__ w, __nv_bfloat16* __restrict__ q,
                          const float* __restrict__ Bfc, __nv_bfloat16* __restrict__ L1,
                          const float* __restrict__ Bpr, __nv_bfloat16* __restrict__ L2) {
    if (blockIdx.x < 4096) {
        float s = load_scale(&g_amax[1]);
        const long long n4 = ((long long)Hh * D) >> 2;
        long long i = (long long)blockIdx.x * blockDim.x + threadIdx.x;
        long long stride = 4096LL * blockDim.x;
        for (; i < n4; i += stride) {
            float4 v = *(const float4*)(w + i * 4);
            float k0 = qclamp(v.x, s), k1 = qclamp(v.y, s);
            float k2 = qclamp(v.z, s), k3 = qclamp(v.w, s);
            ((__nv_bfloat162*)q)[i * 2]     = __halves2bfloat162(__float2bfloat16(k0), __float2bfloat16(k1));
            ((__nv_bfloat162*)q)[i * 2 + 1] = __halves2bfloat162(__float2bfloat16(k2), __float2bfloat16(k3));
        }
    } else {
        int bx = blockIdx.x - 4096;  // 64 blocks
        // L side layout per n: [L_hi(0..15) | L_lo(16..31) | L_hi(32..47)]
        for (int i = bx * 256 + threadIdx.x; i < Hh * R; i += 64 * 256) {
            int n = i >> 4, r = i & 15;
            float v = Bfc[i];
            __nv_bfloat16 hi = __float2bfloat16(v);
            __nv_bfloat16 lo = __float2bfloat16(v - __bfloat162float(hi));
            L1[n * 64 + r] = hi;
            L1[n * 64 + 16 + r] = lo;
            L1[n * 64 + 32 + r] = hi;
        }
        for (int i = bx * 256 + threadIdx.x; i < D * R; i += 64 * 256) {
            int n = i >> 4, r = i & 15;
            float v = Bpr[i];
            __nv_bfloat16 hi = __float2bfloat16(v);
            __nv_bfloat16 lo = __float2bfloat16(v - __bfloat162float(hi));
            L2[n * 64 + r] = hi;
            L2[n * 64 + 16 + r] = lo;
            L2[n * 64 + 32 + r] = hi;
        }
    }
}

// t side layout per m: [t_hi(0..15) | t_hi(16..31) | t_lo(32..47)]
DI void write_text(__nv_bfloat16* text, size_t m, int r, float v) {
    __nv_bfloat16 hi = __float2bfloat16(v);
    __nv_bfloat16 lo = __float2bfloat16(v - __bfloat162float(hi));
    text[m * 64 + r] = hi;
    text[m * 64 + 16 + r] = hi;
    text[m * 64 + 32 + r] = lo;
}

// ---------------- 3: LoRA partials + fused quant(x) + fused reduction -----
__global__ void k_tpart_qr(const float* __restrict__ X, const float* __restrict__ A,
                           int K, float* __restrict__ part,
                           __nv_bfloat16* __restrict__ q,
                           __nv_bfloat16* __restrict__ t1ext) {
    constexpr int KC2 = 256;
    __shared__ float xs[32 * KC2];
    __shared__ float as[16 * (KC2 + 4)];
    __shared__ int s_last;
    float s = load_scale(&g_amax[0]);
    int tid = threadIdx.x;
    int m0 = blockIdx.x * 32;
    int k0 = blockIdx.y * KC2;

    for (int idx = tid; idx < 32 * KC2 / 4; idx += 256) {
        int row = idx / (KC2 / 4), c = idx % (KC2 / 4);
        size_t gidx = (size_t)(m0 + row) * K + k0 + c * 4;
        float4 v = *(const float4*)(X + gidx);
        *(float4*)(xs + row * KC2 + c * 4) = v;
        float q0 = qclamp(v.x, s), q1 = qclamp(v.y, s);
        float q2 = qclamp(v.z, s), q3 = qclamp(v.w, s);
        ((__nv_bfloat162*)q)[gidx / 2]     = __halves2bfloat162(__float2bfloat16(q0), __float2bfloat16(q1));
        ((__nv_bfloat162*)q)[gidx / 2 + 1] = __halves2bfloat162(__float2bfloat16(q2), __float2bfloat16(q3));
    }
    for (int idx = tid; idx < 16 * KC2 / 4; idx += 256) {
        int row = idx / (KC2 / 4), c = idx % (KC2 / 4);
        *(float4*)(as + row * (KC2 + 4) + c * 4) =
            *(const float4*)(A + (size_t)row * K + k0 + c * 4);
    }
    __syncthreads();

    int kt = tid & 7, rg = (tid >> 3) & 3, mg = tid >> 5;
    float acc[4][4];
#pragma unroll
    for (int a = 0; a < 4; a++)
#pragma unroll
        for (int b = 0; b < 4; b++) acc[a][b] = 0.0f;
#pragma unroll
    for (int i = 0; i < 8; i++) {
        int kb = kt * 4 + i * 32;
        float4 xv[4], av[4];
#pragma unroll
        for (int mi = 0; mi < 4; mi++) xv[mi] = *(const float4*)(xs + (mg * 4 + mi) * KC2 + kb);
#pragma unroll
        for (int ri = 0; ri < 4; ri++) av[ri] = *(const float4*)(as + (rg * 4 + ri) * (KC2 + 4) + kb);
#pragma unroll
        for (int mi = 0; mi < 4; mi++)
#pragma unroll
            for (int ri = 0; ri < 4; ri++) {
                float v = acc[mi][ri];
                v = fmaf(xv[mi].x, av[ri].x, v); v = fmaf(xv[mi].y, av[ri].y, v);
                v = fmaf(xv[mi].z, av[ri].z, v); v = fmaf(xv[mi].w, av[ri].w, v);
                acc[mi][ri] = v;
            }
    }
    __syncthreads();
    float* red = xs;
#pragma unroll
    for (int mi = 0; mi < 4; mi++)
#pragma unroll
        for (int ri = 0; ri < 4; ri++)
            red[kt * 512 + (mg * 4 + mi) * 16 + rg * 4 + ri] = acc[mi][ri];
    __syncthreads();
    for (int o = tid; o < 512; o += 256) {
        float v = 0.0f;
#pragma unroll
        for (int c = 0; c < 8; c++) v += red[c * 512 + o];
        part[(size_t)blockIdx.y * ((size_t)M * R) + (size_t)(m0 + (o >> 4)) * 16 + (o & 15)] = v;
    }
    // ---- last-CTA reduction into t1ext (hi/lo split) ----
    __threadfence();
    __syncthreads();
    if (tid == 0) s_last = (atomicAdd(&g_cnt[blockIdx.x], 1u) == gridDim.y - 1) ? 1 : 0;
    __syncthreads();
    if (s_last) {
        __threadfence();
        float sB = load_scale(&g_amax[1]);
        float scale = 2.0f / (s * sB);
        for (int o = tid; o < 512; o += 256) {
            int row = o >> 4, r = o & 15;
            float v = 0.0f;
            for (unsigned c = 0; c < gridDim.y; c++)
                v += part[(size_t)c * ((size_t)M * R) + (size_t)(m0 + row) * 16 + r];
            write_text(t1ext, (size_t)(m0 + row), r, v * scale);
        }
        if (tid == 0) g_cnt[blockIdx.x] = 0u;  // reset for next graph replay
    }
}

// ---------------- 3b: reduce GEMM1 t2-partials -> t2ext (hi/lo split) -----
__global__ void k_t2ext(const float* __restrict__ part, __nv_bfloat16* __restrict__ t2ext,
                        int nchunks) {
    int i = blockIdx.x * blockDim.x + threadIdx.x;  // < M*R
    float v = 0.0f;
    for (int c = 0; c < nchunks; c++) v += part[(size_t)c * ((size_t)M * R) + i];
    float sh = load_scale(&g_amax[3]);
    float sw = load_scale(&g_amax[2]);
    float scale = 2.0f / (sh * sw);
    write_text(t2ext, (size_t)(i >> 4), i & 15, v * scale);
}

// ---- fallback mma.sync building blocks (used only in non-'a' pass) -------
DI uint32_t sw_off_f(int row, int kc) { return (uint32_t)((row * 4 + (kc ^ ((row >> 1) & 3))) << 4); }

DI void load_stage_half(const __nv_bfloat16* base, char* dst, int r0, int rs,
                        int kbase, int tid) {
#pragma unroll
    for (int i = 0; i < 2; i++) {
        int id = tid + i * 256;
        int row = id >> 2, kc = id & 3;
        cp16(dst + sw_off_f(row, kc), base + (size_t)(r0 + row) * rs + kbase + kc * 8);
    }
}

DI void compute_stage_f(const char* As, const char* Bs, float (&acc)[4][4][4],
                        int lane, int wm, int wn) {
#pragma unroll
    for (int ks = 0; ks < 2; ks++) {
        uint32_t a[4][4], b[4][2];
#pragma unroll
        for (int mf = 0; mf < 4; mf++) {
            int row = wm * 64 + mf * 16 + (lane & 15);
            int kc = ks * 2 + (lane >> 4);
            ldm_x4(a[mf][0], a[mf][1], a[mf][2], a[mf][3], As + sw_off_f(row, kc));
        }
#pragma unroll
        for (int bg = 0; bg < 2; bg++) {
            int row = wn * 32 + bg * 16 + (lane & 7) + ((lane >> 4) << 3);
            int kc = ks * 2 + ((lane >> 3) & 1);
            uint32_t r0, r1, r2, r3;
            ldm_x4(r0, r1, r2, r3, Bs + sw_off_f(row, kc));
            b[bg * 2][0] = r0; b[bg * 2][1] = r1;
            b[bg * 2 + 1][0] = r2; b[bg * 2 + 1][1] = r3;
        }
#pragma unroll
        for (int mf = 0; mf < 4; mf++)
#pragma unroll
            for (int nf = 0; nf < 4; nf++) mma16816(acc[mf][nf], a[mf], b[nf]);
    }
}

// ---------------- 4: main GEMM (dual-path, lora folded into K-ext) --------
// 256x128 tile; 2 CTAs/SM so epilogue of one overlaps mainloop of the other.
template <bool GELU>
__global__ __launch_bounds__(256, 2) void k_gemm_tc(
    const __nv_bfloat16* __restrict__ Ag, const __nv_bfloat16* __restrict__ Bg,
    const __nv_bfloat16* __restrict__ ExtA, const __nv_bfloat16* __restrict__ ExtB,
    const float* __restrict__ bias, const unsigned* __restrict__ sAp,
    const unsigned* __restrict__ sBp, float* __restrict__ C,
    unsigned* __restrict__ amax_out, const float* __restrict__ Anext,
    float* __restrict__ tpart_out, int N, int K) {
    extern __shared__ char ds_raw[];
    int tid = threadIdx.x;
    int lane = tid & 31, wid = tid >> 5;
    int m0 = blockIdx.y * TM, n0 = blockIdx.x * TN;

#if HAS_TCGEN05
    __shared__ __align__(8) unsigned long long s_mbar[NSTAGE];
    __shared__ uint32_t s_tmem;

    uint32_t dsu_raw = smaddr(ds_raw);
    uint32_t dsb = (dsu_raw + 1023u) & ~1023u;
    char* ds = ds_raw + (dsb - dsu_raw);

    if (tid == 0)
        for (int s = 0; s < NSTAGE; s++) mbar_init(smaddr(&s_mbar[s]), 1);
    if (wid == 0) {
        asm volatile("tcgen05.alloc.cta_group::1.sync.aligned.shared::cta.b32 [%0], %1;"
                     ::"r"(smaddr(&s_tmem)), "r"(256u) : "memory");
        asm volatile("tcgen05.relinquish_alloc_permit.cta_group::1.sync.aligned;");
    }
    __syncthreads();
    uint32_t tb = s_tmem;

    const int NCk = K / KC;       // regular chunks
    const int NCT = NCk + 1;      // + lora ext chunk
    int ph[NSTAGE] = {0, 0};

    auto load_tile = [&](char* stage, int ci) {
        const __nv_bfloat16* Ab = (ci == NCk) ? ExtA : Ag;
        const __nv_bfloat16* Bb = (ci == NCk) ? ExtB : Bg;
        int rs = (ci == NCk) ? 64 : K;
        int kb = (ci == NCk) ? 0 : ci * KC;
#pragma unroll
        for (int i = 0; i < 8; i++) {               // A: 256 rows x 128B
            int id = tid + (i << 8);
            int r = id >> 3, c = id & 7;
            cp16(stage + r * 128 + (((c ^ (r & 7)) << 4)),
                 Ab + (size_t)(m0 + r) * rs + kb + (c << 3));
        }
#pragma unroll
        for (int i = 0; i < 4; i++) {               // B: 128 rows x 128B
            int id = tid + (i << 8);
            int r = id >> 3, c = id & 7;
            cp16(stage + TM * 128 + r * 128 + ((c ^ (r & 7)) << 4),
                 Bb + (size_t)(n0 + r) * rs + kb + (c << 3));
        }
        cp_commit();
    };

    load_tile(ds, 0);
    load_tile(ds + STAGE_BYTES, 1);

    for (int c = 0; c < NCT; c++) {
        int s = c & 1;
        if (c + 1 < NCT) cp_wait<1>(); else cp_wait<0>();
        __syncthreads();
        if (tid == 0) {
            fence_async();
            uint64_t ad = mkdesc(dsb + s * STAGE_BYTES);
            uint64_t bd = mkdesc(dsb + s * STAGE_BYTES + TM * 128);
#pragma unroll
            for (int ks = 0; ks < KC / 16; ks++) {
                uint32_t en = (c > 0 || ks > 0) ? 1u : 0u;
                tc_mma(tb,       ad + ks * 2,        bd + ks * 2, IDESC, en);
                tc_mma(tb + 128, ad + ks * 2 + 1024, bd + ks * 2, IDESC, en);
            }
            tc_commit(smaddr(&s_mbar[s]));
        }
        if (c + 2 < NCT) {
            mbar_wait(smaddr(&s_mbar[s]), ph[s]); ph[s] ^= 1;
            load_tile(ds + s * STAGE_BYTES, c + 2);
        }
    }
    { int sf = (NCT - 1) & 1; mbar_wait(smaddr(&s_mbar[sf]), ph[sf]); }
    tmem_fence_after();
    __syncthreads();

    // ---- epilogue (scale + bias + gelu + amax + t2-partials) ----
    float sAB = load_scale(sAp) * load_scale(sBp);
    float* Bs  = (float*)ds;            // [TN] bias (512B)
    float* Stg = (float*)(ds + 1024);   // 8 warps x 32x36 floats (36864B)
    float* Asm = (float*)(ds + 37888);  // [16][128] Anext tile (8KB, GELU only)

    if (tid < TN) Bs[tid] = bias[n0 + tid];
    if (GELU) {
        for (int i = tid; i < 512; i += 256) {
            int r = i >> 5, c4 = i & 31;
            ((float4*)Asm)[i] = *(const float4*)(Anext + (size_t)r * N + n0 + c4 * 4);
        }
    }
    __syncthreads();

    int blk = wid >> 2;
    int rowbase = blk * 128 + (wid & 3) * 32;
    int row_local = rowbase + lane;

    unsigned long long s2pk = pk2(sAB, sAB);
    float amx = 0.0f;
    unsigned long long tacc2[16];
    if (GELU) {
#pragma unroll
        for (int r = 0; r < 16; r++) tacc2[r] = 0ull;
    }
    float* stg = Stg + wid * (32 * 36);
    size_t crowbase = (size_t)(m0 + rowbase) * N + n0;

    for (int cb = 0; cb < TN; cb += 32) {
        uint32_t d[32];
        LDTM32(d, tb + blk * 128 + cb);
        tmem_wait_ld();
        float vout[32];
#pragma unroll
        for (int j = 0; j < 16; j++) {
            int n2 = cb + 2 * j;
            unsigned long long d2 = pk2(__uint_as_float(d[2 * j]), __uint_as_float(d[2 * j + 1]));
            unsigned long long v2 = fma2(s2pk, d2, pk2(Bs[n2], Bs[n2 + 1]));
            float v0, v1; upk2(v0, v1, v2);
            if (GELU) {
                v0 = 0.5f * v0 * (1.0f + erff(v0 * 0.70710678118654752f));
                v1 = 0.5f * v1 * (1.0f + erff(v1 * 0.70710678118654752f));
                amx = fmaxf(amx, fmaxf(fabsf(v0), fabsf(v1)));
            }
            vout[2 * j] = v0; vout[2 * j + 1] = v1;
        }
        if (GELU) {
            unsigned long long vp[16];
#pragma unroll
            for (int j = 0; j < 16; j++) vp[j] = pk2(vout[2 * j], vout[2 * j + 1]);
#pragma unroll
            for (int r = 0; r < 16; r++) {
                const unsigned long long* ap = (const unsigned long long*)(Asm + r * 128 + cb);
                unsigned long long t = tacc2[r];
#pragma unroll
                for (int j = 0; j < 16; j++) t = fma2(vp[j], ap[j], t);
                tacc2[r] = t;
            }
        }
#pragma unroll
        for (int q = 0; q < 8; q++) *(float4*)(stg + lane * 36 + q * 4) = *(float4*)(vout + q * 4);
        __syncwarp();
#pragma unroll
        for (int rr = 0; rr < 8; rr++) {
            int r = rr * 4 + (lane >> 3);
            float4 v = *(const float4*)(stg + r * 36 + (lane & 7) * 4);
            *(float4*)(C + crowbase + (size_t)r * N + cb + (lane & 7) * 4) = v;
        }
        __syncwarp();
    }
    if (GELU) {
        float tv[16];
#pragma unroll
        for (int r = 0; r < 16; r++) { float a, b; upk2(a, b, tacc2[r]); tv[r] = a + b; }
        float* pout = tpart_out + (size_t)blockIdx.x * ((size_t)M * R) +
                      (size_t)(m0 + row_local) * 16;
#pragma unroll
        for (int q = 0; q < 4; q++) *(float4*)(pout + q * 4) = *(float4*)(tv + q * 4);
        amx = warp_max(amx);
        if (lane == 0) atomicMax(amax_out, __float_as_uint(amx));
    }
    tmem_fence_before();
    __syncthreads();
    if (wid == 0)
        asm volatile("tcgen05.dealloc.cta_group::1.sync.aligned.b32 %0, %1;"
                     ::"r"(tb), "r"(256u));

#else  // ---------------- fallback: mma.sync, 2 m-quadrants ----------------
    char* ds = ds_raw;
    char* As0 = ds;
    char* Bs0 = ds + 8192;
    char* As1 = ds + 16384;
    char* Bs1 = ds + 24576;
    int wm = wid >> 2, wn = wid & 3;
    float sAB = load_scale(sAp) * load_scale(sBp);
    float amx_all = 0.0f;

    int KT = K / 32;
    int KTT = KT + 2;  // 2 extra 32-col chunks from the 64-col ext

    for (int mq = 0; mq < 2; mq++) {
        int m0q = m0 + mq * 128;
        int n0q = n0;
        __syncthreads();

        float acc[4][4][4];
#pragma unroll
        for (int a = 0; a < 4; a++)
#pragma unroll
            for (int b = 0; b < 4; b++)
#pragma unroll
                for (int c = 0; c < 4; c++) acc[a][b][c] = 0.0f;

        auto load_t = [&](char* As, char* Bs, int t) {
            if (t < KT) {
                load_stage_half(Ag, As, m0q, K, t * 32, tid);
                load_stage_half(Bg, Bs, n0q, K, t * 32, tid);
            } else {
                load_stage_half(ExtA, As, m0q, 64, (t - KT) * 32, tid);
                load_stage_half(ExtB, Bs, n0q, 64, (t - KT) * 32, tid);
            }
        };

        load_t(As0, Bs0, 0);
        cp_commit();
        for (int t = 0; t < KTT; ++t) {
            if (t + 1 < KTT) {
                char* As = ((t + 1) & 1) ? As1 : As0;
                char* Bs = ((t + 1) & 1) ? Bs1 : Bs0;
                load_t(As, Bs, t + 1);
            }
            cp_commit();
            cp_wait<1>();
            __syncthreads();
            {
                const char* As = (t & 1) ? As1 : As0;
                const char* Bs = (t & 1) ? Bs1 : Bs0;
                compute_stage_f(As, Bs, acc, lane, wm, wn);
            }
            __syncthreads();
        }

        float* Bt = (float*)ds;
        for (int i = tid; i < 128; i += 256) Bt[i] = bias[n0q + i];
        __syncthreads();

#pragma unroll
        for (int mf = 0; mf < 4; mf++)
#pragma unroll
            for (int rh = 0; rh < 2; rh++) {
                int ml = wm * 64 + mf * 16 + (lane >> 2) + rh * 8;
                size_t grow = (size_t)(m0q + ml) * N + n0q;
#pragma unroll
                for (int nf = 0; nf < 4; nf++) {
                    int nl0 = wn * 32 + nf * 8 + (lane & 3) * 2;
                    float v0 = sAB * acc[mf][nf][rh * 2 + 0] + Bt[nl0];
                    float v1 = sAB * acc[mf][nf][rh * 2 + 1] + Bt[nl0 + 1];
                    if (GELU) {
                        v0 = 0.5f * v0 * (1.0f + erff(v0 * 0.70710678118654752f));
                        v1 = 0.5f * v1 * (1.0f + erff(v1 * 0.70710678118654752f));
                        amx_all = fmaxf(amx_all, fmaxf(fabsf(v0), fabsf(v1)));
                    }
                    *(float2*)(C + grow + nl0) = make_float2(v0, v1);
                }
            }
        __syncthreads();
    }
    if (GELU) {
        amx_all = warp_max(amx_all);
        if (lane == 0) atomicMax(amax_out, __float_as_uint(amx_all));
        __threadfence();
        __syncthreads();
        int row = tid;
        float tacc[16];
#pragma unroll
        for (int r = 0; r < 16; r++) tacc[r] = 0.0f;
        for (int n = 0; n < TN; n++) {
            float v = C[(size_t)(m0 + row) * N + n0 + n];
#pragma unroll
            for (int r = 0; r < 16; r++)
                tacc[r] = fmaf(v, Anext[(size_t)r * N + n0 + n], tacc[r]);
        }
        float* pout = tpart_out + (size_t)blockIdx.x * ((size_t)M * R) +
                      (size_t)(m0 + row) * 16;
#pragma unroll
        for (int q = 0; q < 4; q++) *(float4*)(pout + q * 4) = *(float4*)(tacc + q * 4);
    }
#endif
}

// ---------------- launcher ----------------------------------------------
extern "C" void kernel_launch(void* const* d_in, const int* in_sizes, int n_in,
                              void* d_out, int out_size) {
    const float* x      = (const float*)d_in[0];
    const float* w_fc   = (const float*)d_in[1];
    const float* b_fc   = (const float*)d_in[2];
    const float* A_fc   = (const float*)d_in[3];
    const float* B_fc   = (const float*)d_in[4];
    const float* w_proj = (const float*)d_in[5];
    const float* b_proj = (const float*)d_in[6];
    const float* A_proj = (const float*)d_in[7];
    const float* B_proj = (const float*)d_in[8];
    float* out = (float*)d_out;

    void *pKx, *pKwfc, *pKwpr, *ph, *pKh, *pt1e, *pt2e, *pL1, *pL2, *ptp, *pam;
    cudaGetSymbolAddress(&pKx, g_Kx);
    cudaGetSymbolAddress(&pKwfc, g_Kwfc);
    cudaGetSymbolAddress(&pKwpr, g_Kwpr);
    cudaGetSymbolAddress(&ph, g_h);
    cudaGetSymbolAddress(&pKh, g_Kh);
    cudaGetSymbolAddress(&pt1e, g_t1ext);
    cudaGetSymbolAddress(&pt2e, g_t2ext);
    cudaGetSymbolAddress(&pL1, g_Lext1);
    cudaGetSymbolAddress(&pL2, g_Lext2);
    cudaGetSymbolAddress(&ptp, g_tpart);
    cudaGetSymbolAddress(&pam, g_amax);

    __nv_bfloat16* Kx    = (__nv_bfloat16*)pKx;
    __nv_bfloat16* Kwfc  = (__nv_bfloat16*)pKwfc;
    __nv_bfloat16* Kwpr  = (__nv_bfloat16*)pKwpr;
    float* hbuf = (float*)ph;
    __nv_bfloat16* Kh    = (__nv_bfloat16*)pKh;
    __nv_bfloat16* t1ext = (__nv_bfloat16*)pt1e;
    __nv_bfloat16* t2ext = (__nv_bfloat16*)pt2e;
    __nv_bfloat16* Lext1 = (__nv_bfloat16*)pL1;
    __nv_bfloat16* Lext2 = (__nv_bfloat16*)pL2;
    float* tp = (float*)ptp;
    unsigned* am = (unsigned*)pam;

    cudaFuncSetAttribute(k_gemm_tc<true>,  cudaFuncAttributeMaxDynamicSharedMemorySize, SMEM_GEMM);
    cudaFuncSetAttribute(k_gemm_tc<false>, cudaFuncAttributeMaxDynamicSharedMemorySize, SMEM_GEMM);

    const long long nWfc = (long long)Hh * D;
    const long long nH   = (long long)M * Hh;

    // 1: amax of x (slot0) and w_fc (slot1) — merged
    k_amax2<<<dim3(2048, 2), 256>>>(x, w_fc);

    // 2: quantize w_fc + build Lext1/Lext2 (hi/lo split)
    k_quantw1<<<4160, 256>>>(w_fc, Kwfc, B_fc, Lext1, B_proj, Lext2);

    // 3: LoRA t1 partials + quant(x) + fused reduction -> t1ext
    k_tpart_qr<<<dim3(M / 32, D / 256), 256>>>(x, A_fc, D, tp, Kx, t1ext);

    // 4: GEMM1 (profiled slot): h = gelu(sAB*(Kx@Kwfc^T + ext) + b_fc)
    k_gemm_tc<true><<<dim3(Hh / TN, M / TM), 256, SMEM_GEMM>>>(
        Kx, Kwfc, t1ext, Lext1, b_fc, am + 0, am + 1, hbuf, am + 3, A_proj, tp, Hh, D);

    // 5: amax w_proj (slot2)
    k_amax<<<2048, 256>>>(w_proj, nWfc, am + 2);

    // 6: quantize w_proj
    k_quant<<<4096, 256>>>(w_proj, Kwpr, nWfc, am + 2, 4096);

    // 7: quantize h (needs amax(h) from GEMM1)
    k_quant<<<8192, 256>>>(hbuf, Kh, nH, am + 3, 8192);

    // 8: reduce t2 partials -> t2ext (hi/lo split)
    k_t2ext<<<(M * R) / 256, 256>>>(tp, t2ext, Hh / TN);

    // 9: GEMM2: out = sAB*(Kh@Kwpr^T + ext) + b_proj
    k_gemm_tc<false><<<dim3(D / TN, M / TM), 256, SMEM_GEMM>>>(
        Kh, Kwpr, t2ext, Lext2, b_proj, am + 3, am + 2, out, nullptr, nullptr, nullptr, D, Hh);
}

// round 16
// speedup vs baseline: 1.1470x; 1.1470x over previous
#include <cuda_runtime.h>
#include <cuda_bf16.h>
#include <cstdint>

#define DI __device__ __forceinline__

// tcgen05 exists only in the arch-specific (sm_103a/sm_100a) pass.
#if defined(__CUDA_ARCH_FEAT_SM103_ALL) || defined(__CUDA_ARCH_FEAT_SM100_ALL)
#define HAS_TCGEN05 1
#else
#define HAS_TCGEN05 0
#endif

// Problem sizes
constexpr int D  = 2048;
constexpr int Hh = 8192;
constexpr int R  = 16;
constexpr int M  = 8192;

// GEMM tiling (tcgen05 bf16 path) — R12-proven: 256x256 tile, 3 stages, 1 CTA/SM
constexpr int TM = 256, TN = 256, KC = 64, NSTAGE = 3;
constexpr int NTHR = 512;                                // 16 warps (epilogue split)
constexpr int STAGE_BYTES = (TM + TN) * 128;            // 64 KB
constexpr int SMEM_GEMM   = NSTAGE * STAGE_BYTES + 1024;
constexpr uint32_t IDESC  = (1u << 4) | (1u << 7) | (1u << 10)  // F32, BF16, BF16
                          | ((TN / 8) << 17) | (8u << 24);      // N=256, M=128
constexpr uint64_t DESC_BASE_SW128 =
    (2ull << 61) | (1ull << 46) | (64ull << 32) | (1ull << 16);

// ---------------- scratch -----------------------------------------------
__device__ __nv_bfloat16 g_Kx[M * D];
__device__ __nv_bfloat16 g_Kwfc[Hh * D];
__device__ __nv_bfloat16 g_Kwpr[D * Hh];
__device__ float         g_h[(size_t)M * Hh];
__device__ __nv_bfloat16 g_Kh[(size_t)M * Hh];
// LoRA fold-in ext chunks, hi/lo split layout (cols 48..63 stay zero forever):
//   t side: [t_hi | t_hi | t_lo | 0],  L side: [L_hi | L_lo | L_hi | 0]
__device__ __nv_bfloat16 g_t1ext[M * 64];
__device__ __nv_bfloat16 g_t2ext[M * 64];
__device__ __nv_bfloat16 g_Lext1[Hh * 64];
__device__ __nv_bfloat16 g_Lext2[D * 64];
__device__ float         g_tpart[64 * M * R];  // 64 chunk slots (2 halves x 32 tiles)
__device__ unsigned      g_amax[4];            // static-zero; amax idempotent across replays
__device__ unsigned      g_cnt[M / 32];        // tpart completion counters (self-resetting)

// ---------------- common helpers ----------------------------------------
DI uint32_t smaddr(const void* p) { return (uint32_t)__cvta_generic_to_shared(p); }
DI void cp16(void* s, const void* g) {
    asm volatile("cp.async.cg.shared.global [%0], [%1], 16;\n" ::"r"(smaddr(s)), "l"(g));
}
DI void cp_commit() { asm volatile("cp.async.commit_group;\n"); }
template <int N> DI void cp_wait() { asm volatile("cp.async.wait_group %0;\n" ::"n"(N)); }

DI float warp_max(float v) {
    for (int o = 16; o; o >>= 1) v = fmaxf(v, __shfl_xor_sync(0xffffffffu, v, o));
    return v;
}
DI float load_scale(const unsigned* slot) {
    return fmaxf(__fdiv_rn(__uint_as_float(*slot), 127.0f), 1e-8f);
}
DI float qclamp(float v, float s) {
    return fminf(fmaxf(rintf(__fdiv_rn(v, s)), -127.f), 127.f);
}

#if HAS_TCGEN05
DI uint64_t mkdesc(uint32_t a) { return DESC_BASE_SW128 | (uint64_t)((a >> 4) & 0x3FFF); }
DI void tc_mma(uint32_t d, uint64_t ad, uint64_t bd, uint32_t idesc, uint32_t en) {
    asm volatile(
        "{\n\t.reg .pred p;\n\tsetp.ne.u32 p, %4, 0;\n\t"
        "tcgen05.mma.cta_group::1.kind::f16 [%0], %1, %2, %3, {%5,%5,%5,%5}, p;\n\t}"
        :: "r"(d), "l"(ad), "l"(bd), "r"(idesc), "r"(en), "r"(0u) : "memory");
}
DI void tc_commit(uint32_t mbar) {
    asm volatile(
        "tcgen05.commit.cta_group::1.mbarrier::arrive::one.shared::cluster.b64 [%0];"
        :: "r"(mbar) : "memory");
}
DI void mbar_init(uint32_t a, uint32_t cnt) {
    asm volatile("mbarrier.init.shared.b64 [%0], %1;" ::"r"(a), "r"(cnt) : "memory");
}
DI void mbar_wait(uint32_t a, uint32_t parity) {
    asm volatile(
        "{\n\t.reg .pred P1;\n\t"
        "WAIT_%=:\n\t"
        "mbarrier.try_wait.parity.acquire.cta.shared::cta.b64 P1, [%0], %1, 0x989680;\n\t"
        "@P1 bra.uni DONE_%=;\n\t"
        "bra.uni WAIT_%=;\n\t"
        "DONE_%=:\n\t}"
        :: "r"(a), "r"(parity) : "memory");
}
DI void fence_async() { asm volatile("fence.proxy.async.shared::cta;" ::: "memory"); }
DI void tmem_fence_after() { asm volatile("tcgen05.fence::after_thread_sync;" ::: "memory"); }
DI void tmem_fence_before() { asm volatile("tcgen05.fence::before_thread_sync;" ::: "memory"); }
DI void tmem_wait_ld() { asm volatile("tcgen05.wait::ld.sync.aligned;" ::: "memory"); }

DI unsigned long long pk2(float a, float b) {
    unsigned long long r; asm("mov.b64 %0, {%1,%2};" : "=l"(r) : "f"(a), "f"(b)); return r;
}
DI void upk2(float& a, float& b, unsigned long long v) {
    asm("mov.b64 {%0,%1}, %2;" : "=f"(a), "=f"(b) : "l"(v));
}
DI unsigned long long fma2(unsigned long long a, unsigned long long b, unsigned long long c) {
    unsigned long long d;
    asm("fma.rn.f32x2 %0, %1, %2, %3;" : "=l"(d) : "l"(a), "l"(b), "l"(c));
    return d;
}

#define LDTM32(r, addr)                                                          \
    asm volatile(                                                                \
        "tcgen05.ld.sync.aligned.32x32b.x32.b32 "                                \
        "{%0,%1,%2,%3,%4,%5,%6,%7,%8,%9,%10,%11,%12,%13,%14,%15,"               \
        "%16,%17,%18,%19,%20,%21,%22,%23,%24,%25,%26,%27,%28,%29,%30,%31},[%32];"\
        : "=r"((r)[0]), "=r"((r)[1]), "=r"((r)[2]), "=r"((r)[3]),                \
          "=r"((r)[4]), "=r"((r)[5]), "=r"((r)[6]), "=r"((r)[7]),                \
          "=r"((r)[8]), "=r"((r)[9]), "=r"((r)[10]), "=r"((r)[11]),              \
          "=r"((r)[12]), "=r"((r)[13]), "=r"((r)[14]), "=r"((r)[15]),            \
          "=r"((r)[16]), "=r"((r)[17]), "=r"((r)[18]), "=r"((r)[19]),            \
          "=r"((r)[20]), "=r"((r)[21]), "=r"((r)[22]), "=r"((r)[23]),            \
          "=r"((r)[24]), "=r"((r)[25]), "=r"((r)[26]), "=r"((r)[27]),            \
          "=r"((r)[28]), "=r"((r)[29]), "=r"((r)[30]), "=r"((r)[31])             \
        : "r"(addr))
#endif  // HAS_TCGEN05

// ---------------- 1: merged amax (x -> slot0, w_fc -> slot1) --------------
__global__ void k_amax2(const float* __restrict__ p0, const float* __restrict__ p1) {
    const float* p = blockIdx.y ? p1 : p0;
    const long long n = (long long)M * D;
    float m = 0.0f;
    long long i = ((long long)blockIdx.x * blockDim.x + threadIdx.x) * 4;
    long long stride = (long long)gridDim.x * blockDim.x * 4;
    for (; i < n; i += stride) {
        float4 v = *(const float4*)(p + i);
        m = fmaxf(m, fmaxf(fmaxf(fabsf(v.x), fabsf(v.y)), fmaxf(fabsf(v.z), fabsf(v.w))));
    }
    m = warp_max(m);
    if ((threadIdx.x & 31) == 0) atomicMax(&g_amax[blockIdx.y], __float_as_uint(m));
}

// ---------------- 1b: single amax (w_proj -> slot2) -----------------------
__global__ void k_amax(const float* __restrict__ p, long long n, unsigned* __restrict__ slot) {
    float m = 0.0f;
    long long i = ((long long)blockIdx.x * blockDim.x + threadIdx.x) * 4;
    long long stride = (long long)gridDim.x * blockDim.x * 4;
    for (; i < n; i += stride) {
        float4 v = *(const float4*)(p + i);
        m = fmaxf(m, fmaxf(fmaxf(fabsf(v.x), fabsf(v.y)), fmaxf(fabsf(v.z), fabsf(v.w))));
    }
    m = warp_max(m);
    if ((threadIdx.x & 31) == 0) atomicMax(slot, __float_as_uint(m));
}

// ---------------- 2: quantize to integer-valued bf16 ----------------------
__global__ void k_quant(const float* __restrict__ p, __nv_bfloat16* __restrict__ q,
                        long long n, const unsigned* __restrict__ slot,
                        long long nblk) {
    float s = load_scale(slot);
    long long i = (long long)blockIdx.x * blockDim.x + threadIdx.x;
    long long stride = nblk * blockDim.x;
    long long n4 = n >> 2;
    for (; i < n4; i += stride) {
        float4 v = *(const float4*)(p + i * 4);
        float k0 = qclamp(v.x, s), k1 = qclamp(v.y, s);
        float k2 = qclamp(v.z, s), k3 = qclamp(v.w, s);
        ((__nv_bfloat162*)q)[i * 2]     = __halves2bfloat162(__float2bfloat16(k0), __float2bfloat16(k1));
        ((__nv_bfloat162*)q)[i * 2 + 1] = __halves2bfloat162(__float2bfloat16(k2), __float2bfloat16(k3));
    }
}

// ---------------- 2b: quant w_fc + build Lext1/Lext2 (hi/lo split) --------
__global__ void k_quantw1(const float* __restrict__ w, __nv_bfloat16* __restrict__ q,
                          const float* __restrict__ Bfc, __nv_bfloat16* __restrict__ L1,
                          const float* __restrict__ Bpr, __nv_bfloat16* __restrict__ L2) {
    if (blockIdx.x < 4096) {
        float s = load_scale(&g_amax[1]);
        const long long n4 = ((long long)Hh * D) >> 2;
        long long i = (long long)blockIdx.x * blockDim.x + threadIdx.x;
        long long stride = 4096LL * blockDim.x;
        for (; i < n4; i += stride) {
            float4 v = *(const float4*)(w + i * 4);
            float k0 = qclamp(v.x, s), k1 = qclamp(v.y, s);
            float k2 = qclamp(v.z, s), k3 = qclamp(v.w, s);
            ((__nv_bfloat162*)q)[i * 2]     = __halves2bfloat162(__float2bfloat16(k0), __float2bfloat16(k1));
            ((__nv_bfloat162*)q)[i * 2 + 1] = __halves2bfloat162(__float2bfloat16(k2), __float2bfloat16(k3));
        }
    } else {
        int bx = blockIdx.x - 4096;  // 64 blocks
        // L side layout per n: [L_hi(0..15) | L_lo(16..31) | L_hi(32..47)]
        for (int i = bx * 256 + threadIdx.x; i < Hh * R; i += 64 * 256) {
            int n = i >> 4, r = i & 15;
            float v = Bfc[i];
            __nv_bfloat16 hi = __float2bfloat16(v);
            __nv_bfloat16 lo = __float2bfloat16(v - __bfloat162float(hi));
            L1[n * 64 + r] = hi;
            L1[n * 64 + 16 + r] = lo;
            L1[n * 64 + 32 + r] = hi;
        }
        for (int i = bx * 256 + threadIdx.x; i < D * R; i += 64 * 256) {
            int n = i >> 4, r = i & 15;
            float v = Bpr[i];
            __nv_bfloat16 hi = __float2bfloat16(v);
            __nv_bfloat16 lo = __float2bfloat16(v - __bfloat162float(hi));
            L2[n * 64 + r] = hi;
            L2[n * 64 + 16 + r] = lo;
            L2[n * 64 + 32 + r] = hi;
        }
    }
}

// t side layout per m: [t_hi(0..15) | t_hi(16..31) | t_lo(32..47)]
DI void write_text(__nv_bfloat16* text, size_t m, int r, float v) {
    __nv_bfloat16 hi = __float2bfloat16(v);
    __nv_bfloat16 lo = __float2bfloat16(v - __bfloat162float(hi));
    text[m * 64 + r] = hi;
    text[m * 64 + 16 + r] = hi;
    text[m * 64 + 32 + r] = lo;
}

// ---------------- 3: LoRA partials + fused quant(x) + fused reduction -----
__global__ void k_tpart_qr(const float* __restrict__ X, const float* __restrict__ A,
                           int K, float* __restrict__ part,
                           __nv_bfloat16* __restrict__ q,
                           __nv_bfloat16* __restrict__ t1ext) {
    constexpr int KC2 = 256;
    __shared__ float xs[32 * KC2];
    __shared__ float as[16 * (KC2 + 4)];
    __shared__ int s_last;
    float s = load_scale(&g_amax[0]);
    int tid = threadIdx.x;
    int m0 = blockIdx.x * 32;
    int k0 = blockIdx.y * KC2;

    for (int idx = tid; idx < 32 * KC2 / 4; idx += 256) {
        int row = idx / (KC2 / 4), c = idx % (KC2 / 4);
        size_t gidx = (size_t)(m0 + row) * K + k0 + c * 4;
        float4 v = *(const float4*)(X + gidx);
        *(float4*)(xs + row * KC2 + c * 4) = v;
        float q0 = qclamp(v.x, s), q1 = qclamp(v.y, s);
        float q2 = qclamp(v.z, s), q3 = qclamp(v.w, s);
        ((__nv_bfloat162*)q)[gidx / 2]     = __halves2bfloat162(__float2bfloat16(q0), __float2bfloat16(q1));
        ((__nv_bfloat162*)q)[gidx / 2 + 1] = __halves2bfloat162(__float2bfloat16(q2), __float2bfloat16(q3));
    }
    for (int idx = tid; idx < 16 * KC2 / 4; idx += 256) {
        int row = idx / (KC2 / 4), c = idx % (KC2 / 4);
        *(float4*)(as + row * (KC2 + 4) + c * 4) =
            *(const float4*)(A + (size_t)row * K + k0 + c * 4);
    }
    __syncthreads();

    int kt = tid & 7, rg = (tid >> 3) & 3, mg = tid >> 5;
    float acc[4][4];
#pragma unroll
    for (int a = 0; a < 4; a++)
#pragma unroll
        for (int b = 0; b < 4; b++) acc[a][b] = 0.0f;
#pragma unroll
    for (int i = 0; i < 8; i++) {
        int kb = kt * 4 + i * 32;
        float4 xv[4], av[4];
#pragma unroll
        for (int mi = 0; mi < 4; mi++) xv[mi] = *(const float4*)(xs + (mg * 4 + mi) * KC2 + kb);
#pragma unroll
        for (int ri = 0; ri < 4; ri++) av[ri] = *(const float4*)(as + (rg * 4 + ri) * (KC2 + 4) + kb);
#pragma unroll
        for (int mi = 0; mi < 4; mi++)
#pragma unroll
            for (int ri = 0; ri < 4; ri++) {
                float v = acc[mi][ri];
                v = fmaf(xv[mi].x, av[ri].x, v); v = fmaf(xv[mi].y, av[ri].y, v);
                v = fmaf(xv[mi].z, av[ri].z, v); v = fmaf(xv[mi].w, av[ri].w, v);
                acc[mi][ri] = v;
            }
    }
    __syncthreads();
    float* red = xs;
#pragma unroll
    for (int mi = 0; mi < 4; mi++)
#pragma unroll
        for (int ri = 0; ri < 4; ri++)
            red[kt * 512 + (mg * 4 + mi) * 16 + rg * 4 + ri] = acc[mi][ri];
    __syncthreads();
    for (int o = tid; o < 512; o += 256) {
        float v = 0.0f;
#pragma unroll
        for (int c = 0; c < 8; c++) v += red[c * 512 + o];
        part[(size_t)blockIdx.y * ((size_t)M * R) + (size_t)(m0 + (o >> 4)) * 16 + (o & 15)] = v;
    }
    // ---- last-CTA reduction into t1ext (hi/lo split) ----
    __threadfence();
    __syncthreads();
    if (tid == 0) s_last = (atomicAdd(&g_cnt[blockIdx.x], 1u) == gridDim.y - 1) ? 1 : 0;
    __syncthreads();
    if (s_last) {
        __threadfence();
        float sB = load_scale(&g_amax[1]);
        float scale = 2.0f / (s * sB);
        for (int o = tid; o < 512; o += 256) {
            int row = o >> 4, r = o & 15;
            float v = 0.0f;
            for (unsigned c = 0; c < gridDim.y; c++)
                v += part[(size_t)c * ((size_t)M * R) + (size_t)(m0 + row) * 16 + r];
            write_text(t1ext, (size_t)(m0 + row), r, v * scale);
        }
        if (tid == 0) g_cnt[blockIdx.x] = 0u;  // reset for next graph replay
    }
}

// ---------------- 3b: reduce GEMM1 t2-partials -> t2ext (hi/lo split) -----
__global__ void k_t2ext(const float* __restrict__ part, __nv_bfloat16* __restrict__ t2ext,
                        int nchunks) {
    int i = blockIdx.x * blockDim.x + threadIdx.x;  // < M*R
    float v = 0.0f;
    for (int c = 0; c < nchunks; c++) v += part[(size_t)c * ((size_t)M * R) + i];
    float sh = load_scale(&g_amax[3]);
    float sw = load_scale(&g_amax[2]);
    float scale = 2.0f / (sh * sw);
    write_text(t2ext, (size_t)(i >> 4), i & 15, v * scale);
}

// ---------------- 4: main GEMM (dual-path, lora folded into K-ext) --------
// 256x256 tile, 512 threads: 16 warps split the epilogue into two cb-halves.
template <bool GELU>
__global__ __launch_bounds__(NTHR, 1) void k_gemm_tc(
    const __nv_bfloat16* __restrict__ Ag, const __nv_bfloat16* __restrict__ Bg,
    const __nv_bfloat16* __restrict__ ExtA, const __nv_bfloat16* __restrict__ ExtB,
    const float* __restrict__ bias, const unsigned* __restrict__ sAp,
    const unsigned* __restrict__ sBp, float* __restrict__ C,
    unsigned* __restrict__ amax_out, const float* __restrict__ Anext,
    float* __restrict__ tpart_out, int N, int K) {
    extern __shared__ char ds_raw[];
    int tid = threadIdx.x;
    int lane = tid & 31, wid = tid >> 5;
    int m0 = blockIdx.y * TM, n0 = blockIdx.x * TN;

#if HAS_TCGEN05
    __shared__ __align__(8) unsigned long long s_mbar[NSTAGE];
    __shared__ uint32_t s_tmem;

    uint32_t dsu_raw = smaddr(ds_raw);
    uint32_t dsb = (dsu_raw + 1023u) & ~1023u;
    char* ds = ds_raw + (dsb - dsu_raw);

    if (tid == 0)
        for (int s = 0; s < NSTAGE; s++) mbar_init(smaddr(&s_mbar[s]), 1);
    if (wid == 0) {
        asm volatile("tcgen05.alloc.cta_group::1.sync.aligned.shared::cta.b32 [%0], %1;"
                     ::"r"(smaddr(&s_tmem)), "r"(512u) : "memory");
        asm volatile("tcgen05.relinquish_alloc_permit.cta_group::1.sync.aligned;");
    }
    __syncthreads();
    uint32_t tb = s_tmem;

    const int NCk = K / KC;       // regular chunks
    const int NCT = NCk + 1;      // + lora ext chunk
    int ph[NSTAGE] = {0, 0, 0};

    auto load_tile = [&](char* stage, int ci) {
        const __nv_bfloat16* Ab = (ci == NCk) ? ExtA : Ag;
        const __nv_bfloat16* Bb = (ci == NCk) ? ExtB : Bg;
        int rs = (ci == NCk) ? 64 : K;
        int kb = (ci == NCk) ? 0 : ci * KC;
#pragma unroll
        for (int i = 0; i < 4; i++) {               // A: 256 rows x 128B, 512 thr
            int id = tid + (i << 9);
            int r = id >> 3, c = id & 7;
            cp16(stage + r * 128 + (((c ^ (r & 7)) << 4)),
                 Ab + (size_t)(m0 + r) * rs + kb + (c << 3));
        }
#pragma unroll
        for (int i = 0; i < 4; i++) {               // B: 256 rows x 128B
            int id = tid + (i << 9);
            int r = id >> 3, c = id & 7;
            cp16(stage + TM * 128 + r * 128 + ((c ^ (r & 7)) << 4),
                 Bb + (size_t)(n0 + r) * rs + kb + (c << 3));
        }
        cp_commit();
    };

    load_tile(ds, 0);
    load_tile(ds + STAGE_BYTES, 1);

    for (int c = 0; c < NCT; c++) {
        int s = c % NSTAGE;
        if (c + 2 < NCT) cp_wait<1>(); else cp_wait<0>();
        __syncthreads();
        if (tid == 0) {
            fence_async();
            uint64_t ad = mkdesc(dsb + s * STAGE_BYTES);
            uint64_t bd = mkdesc(dsb + s * STAGE_BYTES + TM * 128);
#pragma unroll
            for (int ks = 0; ks < KC / 16; ks++) {
                uint32_t en = (c > 0 || ks > 0) ? 1u : 0u;
                tc_mma(tb,       ad + ks * 2,        bd + ks * 2, IDESC, en);
                tc_mma(tb + 256, ad + ks * 2 + 1024, bd + ks * 2, IDESC, en);
            }
            tc_commit(smaddr(&s_mbar[s]));
        }
        if (c + 2 < NCT) {
            int s2 = (c + 2) % NSTAGE;
            if (c >= 1) { mbar_wait(smaddr(&s_mbar[s2]), ph[s2]); ph[s2] ^= 1; }
            load_tile(ds + s2 * STAGE_BYTES, c + 2);
        }
    }
    { int sf = (NCT - 1) % NSTAGE; mbar_wait(smaddr(&s_mbar[sf]), ph[sf]); }
    tmem_fence_after();
    __syncthreads();

    // ---- epilogue: 16 warps, two cb-halves over the same rows ----
    float sAB = load_scale(sAp) * load_scale(sBp);
    float* Bs  = (float*)ds;            // [TN] bias (1KB)
    float* Stg = (float*)(ds + 1024);   // 16 warps x 32x36 floats (73728B)
    float* Asm = (float*)(ds + 74752);  // [16][256] Anext tile (16KB, GELU only)

    if (tid < TN) Bs[tid] = bias[n0 + tid];
    if (GELU) {
        for (int i = tid; i < 1024; i += NTHR) {
            int r = i >> 6, c4 = i & 63;
            ((float4*)Asm)[i] = *(const float4*)(Anext + (size_t)r * N + n0 + c4 * 4);
        }
    }
    __syncthreads();

    int wq = wid & 7;                 // row-group id (0..7)
    int half = wid >> 3;              // cb half (0 or 1)
    int blk = wq >> 2;                // m-block (0 or 1); TMEM subpart = wid%4 = wq%4
    int rowbase = blk * 128 + (wq & 3) * 32;
    int row_local = rowbase + lane;

    unsigned long long s2pk = pk2(sAB, sAB);
    float amx = 0.0f;
    unsigned long long tacc2[16];
    if (GELU) {
#pragma unroll
        for (int r = 0; r < 16; r++) tacc2[r] = 0ull;
    }
    float* stg = Stg + wid * (32 * 36);
    size_t crowbase = (size_t)(m0 + rowbase) * N + n0;

    for (int cb = half * 128; cb < half * 128 + 128; cb += 32) {
        uint32_t d[32];
        LDTM32(d, tb + blk * 256 + cb);
        tmem_wait_ld();
        float vout[32];
#pragma unroll
        for (int j = 0; j < 16; j++) {
            int n2 = cb + 2 * j;
            unsigned long long d2 = pk2(__uint_as_float(d[2 * j]), __uint_as_float(d[2 * j + 1]));
            unsigned long long v2 = fma2(s2pk, d2, pk2(Bs[n2], Bs[n2 + 1]));
            float v0, v1; upk2(v0, v1, v2);
            if (GELU) {
                v0 = 0.5f * v0 * (1.0f + erff(v0 * 0.70710678118654752f));
                v1 = 0.5f * v1 * (1.0f + erff(v1 * 0.70710678118654752f));
                amx = fmaxf(amx, fmaxf(fabsf(v0), fabsf(v1)));
            }
            vout[2 * j] = v0; vout[2 * j + 1] = v1;
        }
        if (GELU) {
            unsigned long long vp[16];
#pragma unroll
            for (int j = 0; j < 16; j++) vp[j] = pk2(vout[2 * j], vout[2 * j + 1]);
#pragma unroll
            for (int r = 0; r < 16; r++) {
                const unsigned long long* ap = (const unsigned long long*)(Asm + r * 256 + cb);
                unsigned long long t = tacc2[r];
#pragma unroll
                for (int j = 0; j < 16; j++) t = fma2(vp[j], ap[j], t);
                tacc2[r] = t;
            }
        }
#pragma unroll
        for (int q = 0; q < 8; q++) *(float4*)(stg + lane * 36 + q * 4) = *(float4*)(vout + q * 4);
        __syncwarp();
#pragma unroll
        for (int rr = 0; rr < 8; rr++) {
            int r = rr * 4 + (lane >> 3);
            float4 v = *(const float4*)(stg + r * 36 + (lane & 7) * 4);
            *(float4*)(C + crowbase + (size_t)r * N + cb + (lane & 7) * 4) = v;
        }
        __syncwarp();
    }
    if (GELU) {
        float tv[16];
#pragma unroll
        for (int r = 0; r < 16; r++) { float a, b; upk2(a, b, tacc2[r]); tv[r] = a + b; }
        float* pout = tpart_out + (size_t)(blockIdx.x * 2 + half) * ((size_t)M * R) +
                      (size_t)(m0 + row_local) * 16;
#pragma unroll
        for (int q = 0; q < 4; q++) *(float4*)(pout + q * 4) = *(float4*)(tv + q * 4);
        amx = warp_max(amx);
        if (lane == 0) atomicMax(amax_out, __float_as_uint(amx));
    }
    tmem_fence_before();
    __syncthreads();
    if (wid == 0)
        asm volatile("tcgen05.dealloc.cta_group::1.sync.aligned.b32 %0, %1;"
                     ::"r"(tb), "r"(512u));

#else  // ------- correctness-only SIMT fallback (never selected on GB300) ----
    float sAB = load_scale(sAp) * load_scale(sBp);
    float amx_all = 0.0f;
    for (int o = tid; o < TM * TN; o += (int)blockDim.x) {
        int rw = o / TN, cl = o % TN;
        const __nv_bfloat16* ar = Ag + (size_t)(m0 + rw) * K;
        const __nv_bfloat16* br = Bg + (size_t)(n0 + cl) * K;
        float acc = 0.0f;
        for (int k = 0; k < K; k++)
            acc = fmaf(__bfloat162float(ar[k]), __bfloat162float(br[k]), acc);
        const __nv_bfloat16* ae = ExtA + (size_t)(m0 + rw) * 64;
        const __nv_bfloat16* be = ExtB + (size_t)(n0 + cl) * 64;
        for (int k = 0; k < 64; k++)
            acc = fmaf(__bfloat162float(ae[k]), __bfloat162float(be[k]), acc);
        float v = sAB * acc + bias[n0 + cl];
        if (GELU) {
            v = 0.5f * v * (1.0f + erff(v * 0.70710678118654752f));
            amx_all = fmaxf(amx_all, fabsf(v));
        }
        C[(size_t)(m0 + rw) * N + n0 + cl] = v;
    }
    if (GELU) {
        amx_all = warp_max(amx_all);
        if ((tid & 31) == 0) atomicMax(amax_out, __float_as_uint(amx_all));
        __threadfence();
        __syncthreads();
        for (int rw = tid; rw < TM; rw += (int)blockDim.x) {
            float tacc[16];
#pragma unroll
            for (int r = 0; r < 16; r++) tacc[r] = 0.0f;
            for (int n = 0; n < TN; n++) {
                float v = C[(size_t)(m0 + rw) * N + n0 + n];
#pragma unroll
                for (int r = 0; r < 16; r++)
                    tacc[r] = fmaf(v, Anext[(size_t)r * N + n0 + n], tacc[r]);
            }
            float* p0 = tpart_out + (size_t)(blockIdx.x * 2) * ((size_t)M * R) +
                        (size_t)(m0 + rw) * 16;
            float* p1 = tpart_out + (size_t)(blockIdx.x * 2 + 1) * ((size_t)M * R) +
                        (size_t)(m0 + rw) * 16;
#pragma unroll
            for (int r = 0; r < 16; r++) { p0[r] = tacc[r]; p1[r] = 0.0f; }
        }
    }
#endif
}

// ---------------- launcher ----------------------------------------------
extern "C" void kernel_launch(void* const* d_in, const int* in_sizes, int n_in,
                              void* d_out, int out_size) {
    const float* x      = (const float*)d_in[0];
    const float* w_fc   = (const float*)d_in[1];
    const float* b_fc   = (const float*)d_in[2];
    const float* A_fc   = (const float*)d_in[3];
    const float* B_fc   = (const float*)d_in[4];
    const float* w_proj = (const float*)d_in[5];
    const float* b_proj = (const float*)d_in[6];
    const float* A_proj = (const float*)d_in[7];
    const float* B_proj = (const float*)d_in[8];
    float* out = (float*)d_out;

    void *pKx, *pKwfc, *pKwpr, *ph, *pKh, *pt1e, *pt2e, *pL1, *pL2, *ptp, *pam;
    cudaGetSymbolAddress(&pKx, g_Kx);
    cudaGetSymbolAddress(&pKwfc, g_Kwfc);
    cudaGetSymbolAddress(&pKwpr, g_Kwpr);
    cudaGetSymbolAddress(&ph, g_h);
    cudaGetSymbolAddress(&pKh, g_Kh);
    cudaGetSymbolAddress(&pt1e, g_t1ext);
    cudaGetSymbolAddress(&pt2e, g_t2ext);
    cudaGetSymbolAddress(&pL1, g_Lext1);
    cudaGetSymbolAddress(&pL2, g_Lext2);
    cudaGetSymbolAddress(&ptp, g_tpart);
    cudaGetSymbolAddress(&pam, g_amax);

    __nv_bfloat16* Kx    = (__nv_bfloat16*)pKx;
    __nv_bfloat16* Kwfc  = (__nv_bfloat16*)pKwfc;
    __nv_bfloat16* Kwpr  = (__nv_bfloat16*)pKwpr;
    float* hbuf = (float*)ph;
    __nv_bfloat16* Kh    = (__nv_bfloat16*)pKh;
    __nv_bfloat16* t1ext = (__nv_bfloat16*)pt1e;
    __nv_bfloat16* t2ext = (__nv_bfloat16*)pt2e;
    __nv_bfloat16* Lext1 = (__nv_bfloat16*)pL1;
    __nv_bfloat16* Lext2 = (__nv_bfloat16*)pL2;
    float* tp = (float*)ptp;
    unsigned* am = (unsigned*)pam;

    cudaFuncSetAttribute(k_gemm_tc<true>,  cudaFuncAttributeMaxDynamicSharedMemorySize, SMEM_GEMM);
    cudaFuncSetAttribute(k_gemm_tc<false>, cudaFuncAttributeMaxDynamicSharedMemorySize, SMEM_GEMM);

    const long long nWfc = (long long)Hh * D;
    const long long nH   = (long long)M * Hh;

    // 1: amax of x (slot0) and w_fc (slot1) — merged
    k_amax2<<<dim3(2048, 2), 256>>>(x, w_fc);

    // 2: quantize w_fc + build Lext1/Lext2 (hi/lo split)
    k_quantw1<<<4160, 256>>>(w_fc, Kwfc, B_fc, Lext1, B_proj, Lext2);

    // 3: LoRA t1 partials + quant(x) + fused reduction -> t1ext
    k_tpart_qr<<<dim3(M / 32, D / 256), 256>>>(x, A_fc, D, tp, Kx, t1ext);

    // 4: GEMM1 (profiled slot): h = gelu(sAB*(Kx@Kwfc^T + ext) + b_fc)
    k_gemm_tc<true><<<dim3(Hh / TN, M / TM), NTHR, SMEM_GEMM>>>(
        Kx, Kwfc, t1ext, Lext1, b_fc, am + 0, am + 1, hbuf, am + 3, A_proj, tp, Hh, D);

    // 5: amax w_proj (slot2)
    k_amax<<<2048, 256>>>(w_proj, nWfc, am + 2);

    // 6: quantize w_proj
    k_quant<<<4096, 256>>>(w_proj, Kwpr, nWfc, am + 2, 4096);

    // 7: quantize h (needs amax(h) from GEMM1)
    k_quant<<<8192, 256>>>(hbuf, Kh, nH, am + 3, 8192);

    // 8: reduce t2 partials -> t2ext (hi/lo split; 64 chunk slots)
    k_t2ext<<<(M * R) / 256, 256>>>(tp, t2ext, 2 * (Hh / TN));

    // 9: GEMM2: out = sAB*(Kh@Kwpr^T + ext) + b_proj
    k_gemm_tc<false><<<dim3(D / TN, M / TM), NTHR, SMEM_GEMM>>>(
        Kh, Kwpr, t2ext, Lext2, b_proj, am + 3, am + 2, out, nullptr, nullptr, nullptr, D, Hh);
}

// round 17
// speedup vs baseline: 1.2436x; 1.0842x over previous
#include <cuda_runtime.h>
#include <cuda_bf16.h>
#include <cstdint>

#define DI __device__ __forceinline__

// tcgen05 exists only in the arch-specific (sm_103a/sm_100a) pass.
#if defined(__CUDA_ARCH_FEAT_SM103_ALL) || defined(__CUDA_ARCH_FEAT_SM100_ALL)
#define HAS_TCGEN05 1
#else
#define HAS_TCGEN05 0
#endif

// Problem sizes
constexpr int D  = 2048;
constexpr int Hh = 8192;
constexpr int R  = 16;
constexpr int M  = 8192;

// GEMM tiling: 256x256 tile, 3 stages, warp-specialized pipeline, 512 threads
constexpr int TM = 256, TN = 256, KC = 64, NSTAGE = 3;
constexpr int NTHR = 512;
constexpr int STAGE_BYTES = (TM + TN) * 128;            // 64 KB
constexpr int SMEM_GEMM   = NSTAGE * STAGE_BYTES + 1024;
constexpr uint32_t IDESC  = (1u << 4) | (1u << 7) | (1u << 10)  // F32, BF16, BF16
                          | ((TN / 8) << 17) | (8u << 24);      // N=256, M=128
constexpr uint64_t DESC_BASE_SW128 =
    (2ull << 61) | (1ull << 46) | (64ull << 32) | (1ull << 16);

// ---------------- scratch -----------------------------------------------
__device__ __nv_bfloat16 g_Kx[M * D];
__device__ __nv_bfloat16 g_Kwfc[Hh * D];
__device__ __nv_bfloat16 g_Kwpr[D * Hh];
__device__ float         g_h[(size_t)M * Hh];
__device__ __nv_bfloat16 g_Kh[(size_t)M * Hh];
// LoRA fold-in ext chunks, hi/lo split layout (cols 48..63 stay zero forever):
//   t side: [t_hi | t_hi | t_lo | 0],  L side: [L_hi | L_lo | L_hi | 0]
__device__ __nv_bfloat16 g_t1ext[M * 64];
__device__ __nv_bfloat16 g_t2ext[M * 64];
__device__ __nv_bfloat16 g_Lext1[Hh * 64];
__device__ __nv_bfloat16 g_Lext2[D * 64];
__device__ float         g_tpart[64 * M * R];  // 64 chunk slots (2 halves x 32 tiles)
__device__ unsigned      g_amax[4];            // static-zero; amax idempotent across replays
__device__ unsigned      g_cnt[M / 32];        // tpart completion counters (self-resetting)

// ---------------- common helpers ----------------------------------------
DI uint32_t smaddr(const void* p) { return (uint32_t)__cvta_generic_to_shared(p); }
DI void cp16(void* s, const void* g) {
    asm volatile("cp.async.cg.shared.global [%0], [%1], 16;\n" ::"r"(smaddr(s)), "l"(g));
}
DI void cp_commit() { asm volatile("cp.async.commit_group;\n"); }
template <int N> DI void cp_wait() { asm volatile("cp.async.wait_group %0;\n" ::"n"(N)); }

DI float warp_max(float v) {
    for (int o = 16; o; o >>= 1) v = fmaxf(v, __shfl_xor_sync(0xffffffffu, v, o));
    return v;
}
DI float load_scale(const unsigned* slot) {
    return fmaxf(__fdiv_rn(__uint_as_float(*slot), 127.0f), 1e-8f);
}
DI float qclamp(float v, float s) {
    return fminf(fmaxf(rintf(__fdiv_rn(v, s)), -127.f), 127.f);
}

#if HAS_TCGEN05
DI uint64_t mkdesc(uint32_t a) { return DESC_BASE_SW128 | (uint64_t)((a >> 4) & 0x3FFF); }
DI void tc_mma(uint32_t d, uint64_t ad, uint64_t bd, uint32_t idesc, uint32_t en) {
    asm volatile(
        "{\n\t.reg .pred p;\n\tsetp.ne.u32 p, %4, 0;\n\t"
        "tcgen05.mma.cta_group::1.kind::f16 [%0], %1, %2, %3, {%5,%5,%5,%5}, p;\n\t}"
        :: "r"(d), "l"(ad), "l"(bd), "r"(idesc), "r"(en), "r"(0u) : "memory");
}
DI void tc_commit(uint32_t mbar) {
    asm volatile(
        "tcgen05.commit.cta_group::1.mbarrier::arrive::one.shared::cluster.b64 [%0];"
        :: "r"(mbar) : "memory");
}
DI void mbar_init(uint32_t a, uint32_t cnt) {
    asm volatile("mbarrier.init.shared.b64 [%0], %1;" ::"r"(a), "r"(cnt) : "memory");
}
DI void mbar_wait(uint32_t a, uint32_t parity) {
    asm volatile(
        "{\n\t.reg .pred P1;\n\t"
        "WAIT_%=:\n\t"
        "mbarrier.try_wait.parity.acquire.cta.shared::cta.b64 P1, [%0], %1, 0x989680;\n\t"
        "@P1 bra.uni DONE_%=;\n\t"
        "bra.uni WAIT_%=;\n\t"
        "DONE_%=:\n\t}"
        :: "r"(a), "r"(parity) : "memory");
}
DI void cp_mbar_arrive(uint32_t a) {
    asm volatile("cp.async.mbarrier.arrive.noinc.shared::cta.b64 [%0];" ::"r"(a) : "memory");
}
DI void fence_async() { asm volatile("fence.proxy.async.shared::cta;" ::: "memory"); }
DI void tmem_fence_after() { asm volatile("tcgen05.fence::after_thread_sync;" ::: "memory"); }
DI void tmem_fence_before() { asm volatile("tcgen05.fence::before_thread_sync;" ::: "memory"); }
DI void tmem_wait_ld() { asm volatile("tcgen05.wait::ld.sync.aligned;" ::: "memory"); }

DI unsigned long long pk2(float a, float b) {
    unsigned long long r; asm("mov.b64 %0, {%1,%2};" : "=l"(r) : "f"(a), "f"(b)); return r;
}
DI void upk2(float& a, float& b, unsigned long long v) {
    asm("mov.b64 {%0,%1}, %2;" : "=f"(a), "=f"(b) : "l"(v));
}
DI unsigned long long fma2(unsigned long long a, unsigned long long b, unsigned long long c) {
    unsigned long long d;
    asm("fma.rn.f32x2 %0, %1, %2, %3;" : "=l"(d) : "l"(a), "l"(b), "l"(c));
    return d;
}

#define LDTM32(r, addr)                                                          \
    asm volatile(                                                                \
        "tcgen05.ld.sync.aligned.32x32b.x32.b32 "                                \
        "{%0,%1,%2,%3,%4,%5,%6,%7,%8,%9,%10,%11,%12,%13,%14,%15,"               \
        "%16,%17,%18,%19,%20,%21,%22,%23,%24,%25,%26,%27,%28,%29,%30,%31},[%32];"\
        : "=r"((r)[0]), "=r"((r)[1]), "=r"((r)[2]), "=r"((r)[3]),                \
          "=r"((r)[4]), "=r"((r)[5]), "=r"((r)[6]), "=r"((r)[7]),                \
          "=r"((r)[8]), "=r"((r)[9]), "=r"((r)[10]), "=r"((r)[11]),              \
          "=r"((r)[12]), "=r"((r)[13]), "=r"((r)[14]), "=r"((r)[15]),            \
          "=r"((r)[16]), "=r"((r)[17]), "=r"((r)[18]), "=r"((r)[19]),            \
          "=r"((r)[20]), "=r"((r)[21]), "=r"((r)[22]), "=r"((r)[23]),            \
          "=r"((r)[24]), "=r"((r)[25]), "=r"((r)[26]), "=r"((r)[27]),            \
          "=r"((r)[28]), "=r"((r)[29]), "=r"((r)[30]), "=r"((r)[31])             \
        : "r"(addr))
#endif  // HAS_TCGEN05

// ---------------- 1: merged amax (x -> slot0, w_fc -> slot1) --------------
__global__ void k_amax2(const float* __restrict__ p0, const float* __restrict__ p1) {
    const float* p = blockIdx.y ? p1 : p0;
    const long long n = (long long)M * D;
    float m = 0.0f;
    long long i = ((long long)blockIdx.x * blockDim.x + threadIdx.x) * 4;
    long long stride = (long long)gridDim.x * blockDim.x * 4;
    for (; i < n; i += stride) {
        float4 v = *(const float4*)(p + i);
        m = fmaxf(m, fmaxf(fmaxf(fabsf(v.x), fabsf(v.y)), fmaxf(fabsf(v.z), fabsf(v.w))));
    }
    m = warp_max(m);
    if ((threadIdx.x & 31) == 0) atomicMax(&g_amax[blockIdx.y], __float_as_uint(m));
}

// ---------------- 1b: single amax (w_proj -> slot2) -----------------------
__global__ void k_amax(const float* __restrict__ p, long long n, unsigned* __restrict__ slot) {
    float m = 0.0f;
    long long i = ((long long)blockIdx.x * blockDim.x + threadIdx.x) * 4;
    long long stride = (long long)gridDim.x * blockDim.x * 4;
    for (; i < n; i += stride) {
        float4 v = *(const float4*)(p + i);
        m = fmaxf(m, fmaxf(fmaxf(fabsf(v.x), fabsf(v.y)), fmaxf(fabsf(v.z), fabsf(v.w))));
    }
    m = warp_max(m);
    if ((threadIdx.x & 31) == 0) atomicMax(slot, __float_as_uint(m));
}

// ---------------- 2: quantize to integer-valued bf16 ----------------------
__global__ void k_quant(const float* __restrict__ p, __nv_bfloat16* __restrict__ q,
                        long long n, const unsigned* __restrict__ slot,
                        long long nblk) {
    float s = load_scale(slot);
    long long i = (long long)blockIdx.x * blockDim.x + threadIdx.x;
    long long stride = nblk * blockDim.x;
    long long n4 = n >> 2;
    for (; i < n4; i += stride) {
        float4 v = *(const float4*)(p + i * 4);
        float k0 = qclamp(v.x, s), k1 = qclamp(v.y, s);
        float k2 = qclamp(v.z, s), k3 = qclamp(v.w, s);
        ((__nv_bfloat162*)q)[i * 2]     = __halves2bfloat162(__float2bfloat16(k0), __float2bfloat16(k1));
        ((__nv_bfloat162*)q)[i * 2 + 1] = __halves2bfloat162(__float2bfloat16(k2), __float2bfloat16(k3));
    }
}

// ---------------- 2b: quant w_fc + build Lext1/Lext2 (hi/lo split) --------
__global__ void k_quantw1(const float* __restrict__ w, __nv_bfloat16* __restrict__ q,
                          const float* __restrict__ Bfc, __nv_bfloat16* __restrict__ L1,
                          const float* __restrict__ Bpr, __nv_bfloat16* __restrict__ L2) {
    if (blockIdx.x < 4096) {
        float s = load_scale(&g_amax[1]);
        const long long n4 = ((long long)Hh * D) >> 2;
        long long i = (long long)blockIdx.x * blockDim.x + threadIdx.x;
        long long stride = 4096LL * blockDim.x;
        for (; i < n4; i += stride) {
            float4 v = *(const float4*)(w + i * 4);
            float k0 = qclamp(v.x, s), k1 = qclamp(v.y, s);
            float k2 = qclamp(v.z, s), k3 = qclamp(v.w, s);
            ((__nv_bfloat162*)q)[i * 2]     = __halves2bfloat162(__float2bfloat16(k0), __float2bfloat16(k1));
            ((__nv_bfloat162*)q)[i * 2 + 1] = __halves2bfloat162(__float2bfloat16(k2), __float2bfloat16(k3));
        }
    } else {
        int bx = blockIdx.x - 4096;  // 64 blocks
        // L side layout per n: [L_hi(0..15) | L_lo(16..31) | L_hi(32..47)]
        for (int i = bx * 256 + threadIdx.x; i < Hh * R; i += 64 * 256) {
            int n = i >> 4, r = i & 15;
            float v = Bfc[i];
            __nv_bfloat16 hi = __float2bfloat16(v);
            __nv_bfloat16 lo = __float2bfloat16(v - __bfloat162float(hi));
            L1[n * 64 + r] = hi;
            L1[n * 64 + 16 + r] = lo;
            L1[n * 64 + 32 + r] = hi;
        }
        for (int i = bx * 256 + threadIdx.x; i < D * R; i += 64 * 256) {
            int n = i >> 4, r = i & 15;
            float v = Bpr[i];
            __nv_bfloat16 hi = __float2bfloat16(v);
            __nv_bfloat16 lo = __float2bfloat16(v - __bfloat162float(hi));
            L2[n * 64 + r] = hi;
            L2[n * 64 + 16 + r] = lo;
            L2[n * 64 + 32 + r] = hi;
        }
    }
}

// t side layout per m: [t_hi(0..15) | t_hi(16..31) | t_lo(32..47)]
DI void write_text(__nv_bfloat16* text, size_t m, int r, float v) {
    __nv_bfloat16 hi = __float2bfloat16(v);
    __nv_bfloat16 lo = __float2bfloat16(v - __bfloat162float(hi));
    text[m * 64 + r] = hi;
    text[m * 64 + 16 + r] = hi;
    text[m * 64 + 32 + r] = lo;
}

// ---------------- 3: LoRA partials + fused quant(x) + fused reduction -----
__global__ void k_tpart_qr(const float* __restrict__ X, const float* __restrict__ A,
                           int K, float* __restrict__ part,
                           __nv_bfloat16* __restrict__ q,
                           __nv_bfloat16* __restrict__ t1ext) {
    constexpr int KC2 = 256;
    __shared__ float xs[32 * KC2];
    __shared__ float as[16 * (KC2 + 4)];
    __shared__ int s_last;
    float s = load_scale(&g_amax[0]);
    int tid = threadIdx.x;
    int m0 = blockIdx.x * 32;
    int k0 = blockIdx.y * KC2;

    for (int idx = tid; idx < 32 * KC2 / 4; idx += 256) {
        int row = idx / (KC2 / 4), c = idx % (KC2 / 4);
        size_t gidx = (size_t)(m0 + row) * K + k0 + c * 4;
        float4 v = *(const float4*)(X + gidx);
        *(float4*)(xs + row * KC2 + c * 4) = v;
        float q0 = qclamp(v.x, s), q1 = qclamp(v.y, s);
        float q2 = qclamp(v.z, s), q3 = qclamp(v.w, s);
        ((__nv_bfloat162*)q)[gidx / 2]     = __halves2bfloat162(__float2bfloat16(q0), __float2bfloat16(q1));
        ((__nv_bfloat162*)q)[gidx / 2 + 1] = __halves2bfloat162(__float2bfloat16(q2), __float2bfloat16(q3));
    }
    for (int idx = tid; idx < 16 * KC2 / 4; idx += 256) {
        int row = idx / (KC2 / 4), c = idx % (KC2 / 4);
        *(float4*)(as + row * (KC2 + 4) + c * 4) =
            *(const float4*)(A + (size_t)row * K + k0 + c * 4);
    }
    __syncthreads();

    int kt = tid & 7, rg = (tid >> 3) & 3, mg = tid >> 5;
    float acc[4][4];
#pragma unroll
    for (int a = 0; a < 4; a++)
#pragma unroll
        for (int b = 0; b < 4; b++) acc[a][b] = 0.0f;
#pragma unroll
    for (int i = 0; i < 8; i++) {
        int kb = kt * 4 + i * 32;
        float4 xv[4], av[4];
#pragma unroll
        for (int mi = 0; mi < 4; mi++) xv[mi] = *(const float4*)(xs + (mg * 4 + mi) * KC2 + kb);
#pragma unroll
        for (int ri = 0; ri < 4; ri++) av[ri] = *(const float4*)(as + (rg * 4 + ri) * (KC2 + 4) + kb);
#pragma unroll
        for (int mi = 0; mi < 4; mi++)
#pragma unroll
            for (int ri = 0; ri < 4; ri++) {
                float v = acc[mi][ri];
                v = fmaf(xv[mi].x, av[ri].x, v); v = fmaf(xv[mi].y, av[ri].y, v);
                v = fmaf(xv[mi].z, av[ri].z, v); v = fmaf(xv[mi].w, av[ri].w, v);
                acc[mi][ri] = v;
            }
    }
    __syncthreads();
    float* red = xs;
#pragma unroll
    for (int mi = 0; mi < 4; mi++)
#pragma unroll
        for (int ri = 0; ri < 4; ri++)
            red[kt * 512 + (mg * 4 + mi) * 16 + rg * 4 + ri] = acc[mi][ri];
    __syncthreads();
    for (int o = tid; o < 512; o += 256) {
        float v = 0.0f;
#pragma unroll
        for (int c = 0; c < 8; c++) v += red[c * 512 + o];
        part[(size_t)blockIdx.y * ((size_t)M * R) + (size_t)(m0 + (o >> 4)) * 16 + (o & 15)] = v;
    }
    // ---- last-CTA reduction into t1ext (hi/lo split) ----
    __threadfence();
    __syncthreads();
    if (tid == 0) s_last = (atomicAdd(&g_cnt[blockIdx.x], 1u) == gridDim.y - 1) ? 1 : 0;
    __syncthreads();
    if (s_last) {
        __threadfence();
        float sB = load_scale(&g_amax[1]);
        float scale = 2.0f / (s * sB);
        for (int o = tid; o < 512; o += 256) {
            int row = o >> 4, r = o & 15;
            float v = 0.0f;
            for (unsigned c = 0; c < gridDim.y; c++)
                v += part[(size_t)c * ((size_t)M * R) + (size_t)(m0 + row) * 16 + r];
            write_text(t1ext, (size_t)(m0 + row), r, v * scale);
        }
        if (tid == 0) g_cnt[blockIdx.x] = 0u;  // reset for next graph replay
    }
}

// ---------------- 3b: reduce GEMM1 t2-partials -> t2ext (hi/lo split) -----
__global__ void k_t2ext(const float* __restrict__ part, __nv_bfloat16* __restrict__ t2ext,
                        int nchunks) {
    int i = blockIdx.x * blockDim.x + threadIdx.x;  // < M*R
    float v = 0.0f;
    for (int c = 0; c < nchunks; c++) v += part[(size_t)c * ((size_t)M * R) + i];
    float sh = load_scale(&g_amax[3]);
    float sw = load_scale(&g_amax[2]);
    float scale = 2.0f / (sh * sw);
    write_text(t2ext, (size_t)(i >> 4), i & 15, v * scale);
}

// ---------------- 4: main GEMM (warp-specialized producer/consumer) -------
// Producers: warps 0-7 fill stages via cp.async + mbarrier arrive.
// MMA issuer: warp 8 lane 0. Epilogue: all 16 warps (two cb-halves).
template <bool GELU>
__global__ __launch_bounds__(NTHR, 1) void k_gemm_tc(
    const __nv_bfloat16* __restrict__ Ag, const __nv_bfloat16* __restrict__ Bg,
    const __nv_bfloat16* __restrict__ ExtA, const __nv_bfloat16* __restrict__ ExtB,
    const float* __restrict__ bias, const unsigned* __restrict__ sAp,
    const unsigned* __restrict__ sBp, float* __restrict__ C,
    unsigned* __restrict__ amax_out, const float* __restrict__ Anext,
    float* __restrict__ tpart_out, int N, int K) {
    extern __shared__ char ds_raw[];
    int tid = threadIdx.x;
    int lane = tid & 31, wid = tid >> 5;
    int m0 = blockIdx.y * TM, n0 = blockIdx.x * TN;

#if HAS_TCGEN05
    __shared__ __align__(8) unsigned long long s_full[NSTAGE], s_empty[NSTAGE], s_done;
    __shared__ uint32_t s_tmem;

    uint32_t dsu_raw = smaddr(ds_raw);
    uint32_t dsb = (dsu_raw + 1023u) & ~1023u;
    char* ds = ds_raw + (dsb - dsu_raw);

    if (tid == 0) {
        for (int s = 0; s < NSTAGE; s++) {
            mbar_init(smaddr(&s_full[s]), 256);   // 256 producer cp-async arrivals
            mbar_init(smaddr(&s_empty[s]), 1);    // 1 tcgen05.commit arrival
        }
        mbar_init(smaddr(&s_done), 1);
    }
    if (wid == 0) {
        asm volatile("tcgen05.alloc.cta_group::1.sync.aligned.shared::cta.b32 [%0], %1;"
                     ::"r"(smaddr(&s_tmem)), "r"(512u) : "memory");
        asm volatile("tcgen05.relinquish_alloc_permit.cta_group::1.sync.aligned;");
    }
    __syncthreads();
    uint32_t tb = s_tmem;

    const int NCk = K / KC;       // regular chunks
    const int NCT = NCk + 1;      // + lora ext chunk

    if (wid < 8) {
        // -------- producer: 256 threads, free-running over stages --------
        int pe[NSTAGE] = {0, 0, 0};
        for (int c = 0; c < NCT; c++) {
            int s = c % NSTAGE;
            if (c >= NSTAGE) { mbar_wait(smaddr(&s_empty[s]), pe[s]); pe[s] ^= 1; }
            char* stage = ds + s * STAGE_BYTES;
            const __nv_bfloat16* Ab = (c == NCk) ? ExtA : Ag;
            const __nv_bfloat16* Bb = (c == NCk) ? ExtB : Bg;
            int rs = (c == NCk) ? 64 : K;
            int kb = (c == NCk) ? 0 : c * KC;
#pragma unroll
            for (int i = 0; i < 8; i++) {          // A: 256 rows x 128B
                int id = tid + (i << 8);
                int r = id >> 3, cc = id & 7;
                cp16(stage + r * 128 + (((cc ^ (r & 7)) << 4)),
                     Ab + (size_t)(m0 + r) * rs + kb + (cc << 3));
            }
#pragma unroll
            for (int i = 0; i < 8; i++) {          // B: 256 rows x 128B
                int id = tid + (i << 8);
                int r = id >> 3, cc = id & 7;
                cp16(stage + TM * 128 + r * 128 + ((cc ^ (r & 7)) << 4),
                     Bb + (size_t)(n0 + r) * rs + kb + (cc << 3));
            }
            cp_mbar_arrive(smaddr(&s_full[s]));
        }
    } else if (wid == 8 && lane == 0) {
        // -------- MMA issuer: single thread --------
        int pf[NSTAGE] = {0, 0, 0};
        for (int c = 0; c < NCT; c++) {
            int s = c % NSTAGE;
            mbar_wait(smaddr(&s_full[s]), pf[s]); pf[s] ^= 1;
            fence_async();
            uint64_t ad = mkdesc(dsb + s * STAGE_BYTES);
            uint64_t bd = mkdesc(dsb + s * STAGE_BYTES + TM * 128);
#pragma unroll
            for (int ks = 0; ks < KC / 16; ks++) {
                uint32_t en = (c > 0 || ks > 0) ? 1u : 0u;
                tc_mma(tb,       ad + ks * 2,        bd + ks * 2, IDESC, en);
                tc_mma(tb + 256, ad + ks * 2 + 1024, bd + ks * 2, IDESC, en);
            }
            tc_commit(smaddr(&s_empty[s]));
        }
        tc_commit(smaddr(&s_done));
    }

    // all threads wait for the full accumulation to finish
    mbar_wait(smaddr(&s_done), 0);
    tmem_fence_after();
    __syncthreads();

    // ---- epilogue: 16 warps, two cb-halves over the same rows ----
    float sAB = load_scale(sAp) * load_scale(sBp);
    float* Bs  = (float*)ds;            // [TN] bias (1KB)
    float* Stg = (float*)(ds + 1024);   // 16 warps x 32x36 floats (73728B)
    float* Asm = (float*)(ds + 74752);  // [16][256] Anext tile (16KB, GELU only)

    if (tid < TN) Bs[tid] = bias[n0 + tid];
    if (GELU) {
        for (int i = tid; i < 1024; i += NTHR) {
            int r = i >> 6, c4 = i & 63;
            ((float4*)Asm)[i] = *(const float4*)(Anext + (size_t)r * N + n0 + c4 * 4);
        }
    }
    __syncthreads();

    int wq = wid & 7;                 // row-group id (0..7)
    int half = wid >> 3;              // cb half (0 or 1)
    int blk = wq >> 2;                // m-block (0 or 1); TMEM subpart = wid%4 = wq%4
    int rowbase = blk * 128 + (wq & 3) * 32;
    int row_local = rowbase + lane;

    unsigned long long s2pk = pk2(sAB, sAB);
    float amx = 0.0f;
    unsigned long long tacc2[16];
    if (GELU) {
#pragma unroll
        for (int r = 0; r < 16; r++) tacc2[r] = 0ull;
    }
    float* stg = Stg + wid * (32 * 36);
    size_t crowbase = (size_t)(m0 + rowbase) * N + n0;

    for (int cb = half * 128; cb < half * 128 + 128; cb += 32) {
        uint32_t d[32];
        LDTM32(d, tb + blk * 256 + cb);
        tmem_wait_ld();
        float vout[32];
#pragma unroll
        for (int j = 0; j < 16; j++) {
            int n2 = cb + 2 * j;
            unsigned long long d2 = pk2(__uint_as_float(d[2 * j]), __uint_as_float(d[2 * j + 1]));
            unsigned long long v2 = fma2(s2pk, d2, pk2(Bs[n2], Bs[n2 + 1]));
            float v0, v1; upk2(v0, v1, v2);
            if (GELU) {
                v0 = 0.5f * v0 * (1.0f + erff(v0 * 0.70710678118654752f));
                v1 = 0.5f * v1 * (1.0f + erff(v1 * 0.70710678118654752f));
                amx = fmaxf(amx, fmaxf(fabsf(v0), fabsf(v1)));
            }
            vout[2 * j] = v0; vout[2 * j + 1] = v1;
        }
        if (GELU) {
            unsigned long long vp[16];
#pragma unroll
            for (int j = 0; j < 16; j++) vp[j] = pk2(vout[2 * j], vout[2 * j + 1]);
#pragma unroll
            for (int r = 0; r < 16; r++) {
                const unsigned long long* ap = (const unsigned long long*)(Asm + r * 256 + cb);
                unsigned long long t = tacc2[r];
#pragma unroll
                for (int j = 0; j < 16; j++) t = fma2(vp[j], ap[j], t);
                tacc2[r] = t;
            }
        }
#pragma unroll
        for (int q = 0; q < 8; q++) *(float4*)(stg + lane * 36 + q * 4) = *(float4*)(vout + q * 4);
        __syncwarp();
#pragma unroll
        for (int rr = 0; rr < 8; rr++) {
            int r = rr * 4 + (lane >> 3);
            float4 v = *(const float4*)(stg + r * 36 + (lane & 7) * 4);
            *(float4*)(C + crowbase + (size_t)r * N + cb + (lane & 7) * 4) = v;
        }
        __syncwarp();
    }
    if (GELU) {
        float tv[16];
#pragma unroll
        for (int r = 0; r < 16; r++) { float a, b; upk2(a, b, tacc2[r]); tv[r] = a + b; }
        float* pout = tpart_out + (size_t)(blockIdx.x * 2 + half) * ((size_t)M * R) +
                      (size_t)(m0 + row_local) * 16;
#pragma unroll
        for (int q = 0; q < 4; q++) *(float4*)(pout + q * 4) = *(float4*)(tv + q * 4);
        amx = warp_max(amx);
        if (lane == 0) atomicMax(amax_out, __float_as_uint(amx));
    }
    tmem_fence_before();
    __syncthreads();
    if (wid == 0)
        asm volatile("tcgen05.dealloc.cta_group::1.sync.aligned.b32 %0, %1;"
                     ::"r"(tb), "r"(512u));

#else  // ------- correctness-only SIMT fallback (never selected on GB300) ----
    float sAB = load_scale(sAp) * load_scale(sBp);
    float amx_all = 0.0f;
    for (int o = tid; o < TM * TN; o += (int)blockDim.x) {
        int rw = o / TN, cl = o % TN;
        const __nv_bfloat16* ar = Ag + (size_t)(m0 + rw) * K;
        const __nv_bfloat16* br = Bg + (size_t)(n0 + cl) * K;
        float acc = 0.0f;
        for (int k = 0; k < K; k++)
            acc = fmaf(__bfloat162float(ar[k]), __bfloat162float(br[k]), acc);
        const __nv_bfloat16* ae = ExtA + (size_t)(m0 + rw) * 64;
        const __nv_bfloat16* be = ExtB + (size_t)(n0 + cl) * 64;
        for (int k = 0; k < 64; k++)
            acc = fmaf(__bfloat162float(ae[k]), __bfloat162float(be[k]), acc);
        float v = sAB * acc + bias[n0 + cl];
        if (GELU) {
            v = 0.5f * v * (1.0f + erff(v * 0.70710678118654752f));
            amx_all = fmaxf(amx_all, fabsf(v));
        }
        C[(size_t)(m0 + rw) * N + n0 + cl] = v;
    }
    if (GELU) {
        amx_all = warp_max(amx_all);
        if ((tid & 31) == 0) atomicMax(amax_out, __float_as_uint(amx_all));
        __threadfence();
        __syncthreads();
        for (int rw = tid; rw < TM; rw += (int)blockDim.x) {
            float tacc[16];
#pragma unroll
            for (int r = 0; r < 16; r++) tacc[r] = 0.0f;
            for (int n = 0; n < TN; n++) {
                float v = C[(size_t)(m0 + rw) * N + n0 + n];
#pragma unroll
                for (int r = 0; r < 16; r++)
                    tacc[r] = fmaf(v, Anext[(size_t)r * N + n0 + n], tacc[r]);
            }
            float* p0 = tpart_out + (size_t)(blockIdx.x * 2) * ((size_t)M * R) +
                        (size_t)(m0 + rw) * 16;
            float* p1 = tpart_out + (size_t)(blockIdx.x * 2 + 1) * ((size_t)M * R) +
                        (size_t)(m0 + rw) * 16;
#pragma unroll
            for (int r = 0; r < 16; r++) { p0[r] = tacc[r]; p1[r] = 0.0f; }
        }
    }
#endif
}

// ---------------- launcher ----------------------------------------------
extern "C" void kernel_launch(void* const* d_in, const int* in_sizes, int n_in,
                              void* d_out, int out_size) {
    const float* x      = (const float*)d_in[0];
    const float* w_fc   = (const float*)d_in[1];
    const float* b_fc   = (const float*)d_in[2];
    const float* A_fc   = (const float*)d_in[3];
    const float* B_fc   = (const float*)d_in[4];
    const float* w_proj = (const float*)d_in[5];
    const float* b_proj = (const float*)d_in[6];
    const float* A_proj = (const float*)d_in[7];
    const float* B_proj = (const float*)d_in[8];
    float* out = (float*)d_out;

    void *pKx, *pKwfc, *pKwpr, *ph, *pKh, *pt1e, *pt2e, *pL1, *pL2, *ptp, *pam;
    cudaGetSymbolAddress(&pKx, g_Kx);
    cudaGetSymbolAddress(&pKwfc, g_Kwfc);
    cudaGetSymbolAddress(&pKwpr, g_Kwpr);
    cudaGetSymbolAddress(&ph, g_h);
    cudaGetSymbolAddress(&pKh, g_Kh);
    cudaGetSymbolAddress(&pt1e, g_t1ext);
    cudaGetSymbolAddress(&pt2e, g_t2ext);
    cudaGetSymbolAddress(&pL1, g_Lext1);
    cudaGetSymbolAddress(&pL2, g_Lext2);
    cudaGetSymbolAddress(&ptp, g_tpart);
    cudaGetSymbolAddress(&pam, g_amax);

    __nv_bfloat16* Kx    = (__nv_bfloat16*)pKx;
    __nv_bfloat16* Kwfc  = (__nv_bfloat16*)pKwfc;
    __nv_bfloat16* Kwpr  = (__nv_bfloat16*)pKwpr;
    float* hbuf = (float*)ph;
    __nv_bfloat16* Kh    = (__nv_bfloat16*)pKh;
    __nv_bfloat16* t1ext = (__nv_bfloat16*)pt1e;
    __nv_bfloat16* t2ext = (__nv_bfloat16*)pt2e;
    __nv_bfloat16* Lext1 = (__nv_bfloat16*)pL1;
    __nv_bfloat16* Lext2 = (__nv_bfloat16*)pL2;
    float* tp = (float*)ptp;
    unsigned* am = (unsigned*)pam;

    cudaFuncSetAttribute(k_gemm_tc<true>,  cudaFuncAttributeMaxDynamicSharedMemorySize, SMEM_GEMM);
    cudaFuncSetAttribute(k_gemm_tc<false>, cudaFuncAttributeMaxDynamicSharedMemorySize, SMEM_GEMM);

    const long long nWfc = (long long)Hh * D;
    const long long nH   = (long long)M * Hh;

    // 1: amax of x (slot0) and w_fc (slot1) — merged
    k_amax2<<<dim3(2048, 2), 256>>>(x, w_fc);

    // 2: quantize w_fc + build Lext1/Lext2 (hi/lo split)
    k_quantw1<<<4160, 256>>>(w_fc, Kwfc, B_fc, Lext1, B_proj, Lext2);

    // 3: LoRA t1 partials + quant(x) + fused reduction -> t1ext
    k_tpart_qr<<<dim3(M / 32, D / 256), 256>>>(x, A_fc, D, tp, Kx, t1ext);

    // 4: GEMM1 (profiled slot): h = gelu(sAB*(Kx@Kwfc^T + ext) + b_fc)
    k_gemm_tc<true><<<dim3(Hh / TN, M / TM), NTHR, SMEM_GEMM>>>(
        Kx, Kwfc, t1ext, Lext1, b_fc, am + 0, am + 1, hbuf, am + 3, A_proj, tp, Hh, D);

    // 5: amax w_proj (slot2)
    k_amax<<<2048, 256>>>(w_proj, nWfc, am + 2);

    // 6: quantize w_proj
    k_quant<<<4096, 256>>>(w_proj, Kwpr, nWfc, am + 2, 4096);

    // 7: quantize h (needs amax(h) from GEMM1)
    k_quant<<<8192, 256>>>(hbuf, Kh, nH, am + 3, 8192);

    // 8: reduce t2 partials -> t2ext (hi/lo split; 64 chunk slots)
    k_t2ext<<<(M * R) / 256, 256>>>(tp, t2ext, 2 * (Hh / TN));

    // 9: GEMM2: out = sAB*(Kh@Kwpr^T + ext) + b_proj
    k_gemm_tc<false><<<dim3(D / TN, M / TM), NTHR, SMEM_GEMM>>>(
        Kh, Kwpr, t2ext, Lext2, b_proj, am + 3, am + 2, out, nullptr, nullptr, nullptr, D, Hh);
}